// round 1
// baseline (speedup 1.0000x reference)
#include <cuda_runtime.h>

// Problem constants
#define Bq   4
#define Tq   4096
#define Cq   2048
#define Hq   16
#define DHq  128
#define Mq   (Bq*Tq)          // 16384

// Scratch (device globals: allocation-free rule)
__device__ float g_q[Mq*Cq];      // [B,H,T,Dh]
__device__ float g_k[Mq*Cq];      // [B,H,T,Dh]
__device__ float g_v[Mq*Cq];      // [B,H,T,Dh]
__device__ float g_att[Mq*Cq];    // [B,T,C]
__device__ float g_kv[Bq*Hq*DHq*DHq];
__device__ float g_ksum[Bq*Hq*DHq];

__device__ __forceinline__ float featmap(float y) {
    // elu(y) + 1
    return y > 0.f ? y + 1.f : __expf(y);
}

// ---------------------------------------------------------------------------
// Tiled NT SGEMM body: C[m,o] = sum_c A[m,c] * W[o,c]
// M=16384, N=2048, K=2048. BM=BN=128, BK=16, 256 threads, 8x8 per thread.
// QKVLAY: write to [B,H,T,Dh] layout (h == blockIdx.y since BN==Dh==128)
// ---------------------------------------------------------------------------
template<bool QKVLAY>
__device__ __forceinline__ void gemm_body(const float* __restrict__ A,
                                          const float* __restrict__ W,
                                          float* __restrict__ out,
                                          bool act)
{
    __shared__ float As[16][128];
    __shared__ float Bs[16][128];
    const int bm  = blockIdx.x * 128;
    const int bn  = blockIdx.y * 128;
    const int tid = threadIdx.x;
    const int tx  = tid & 15;        // 0..15 -> output cols tx*8..
    const int ty  = tid >> 4;        // 0..15 -> output rows ty*8..
    const int lr  = tid >> 1;        // 0..127 load row
    const int lk  = (tid & 1) * 8;   // k offset 0 or 8

    float acc[8][8];
    #pragma unroll
    for (int i = 0; i < 8; i++)
        #pragma unroll
        for (int j = 0; j < 8; j++) acc[i][j] = 0.f;

    const float* ap = A + (size_t)(bm + lr) * Cq + lk;
    const float* bp = W + (size_t)(bn + lr) * Cq + lk;

    for (int k0 = 0; k0 < Cq; k0 += 16) {
        float4 a0 = *(const float4*)(ap + k0);
        float4 a1 = *(const float4*)(ap + k0 + 4);
        float4 b0 = *(const float4*)(bp + k0);
        float4 b1 = *(const float4*)(bp + k0 + 4);
        As[lk+0][lr] = a0.x; As[lk+1][lr] = a0.y; As[lk+2][lr] = a0.z; As[lk+3][lr] = a0.w;
        As[lk+4][lr] = a1.x; As[lk+5][lr] = a1.y; As[lk+6][lr] = a1.z; As[lk+7][lr] = a1.w;
        Bs[lk+0][lr] = b0.x; Bs[lk+1][lr] = b0.y; Bs[lk+2][lr] = b0.z; Bs[lk+3][lr] = b0.w;
        Bs[lk+4][lr] = b1.x; Bs[lk+5][lr] = b1.y; Bs[lk+6][lr] = b1.z; Bs[lk+7][lr] = b1.w;
        __syncthreads();
        #pragma unroll
        for (int kk = 0; kk < 16; kk++) {
            float af[8], bf[8];
            *(float4*)&af[0] = *(const float4*)&As[kk][ty*8];
            *(float4*)&af[4] = *(const float4*)&As[kk][ty*8+4];
            *(float4*)&bf[0] = *(const float4*)&Bs[kk][tx*8];
            *(float4*)&bf[4] = *(const float4*)&Bs[kk][tx*8+4];
            #pragma unroll
            for (int i = 0; i < 8; i++)
                #pragma unroll
                for (int j = 0; j < 8; j++)
                    acc[i][j] += af[i] * bf[j];
        }
        __syncthreads();
    }

    #pragma unroll
    for (int i = 0; i < 8; i++) {
        const int m = bm + ty*8 + i;
        float r[8];
        #pragma unroll
        for (int j = 0; j < 8; j++)
            r[j] = act ? featmap(acc[i][j]) : acc[i][j];
        float* op;
        if (QKVLAY) {
            const int b = m >> 12;          // m / Tq
            const int t = m & (Tq - 1);
            // h == blockIdx.y, d == tx*8+j
            op = out + (((size_t)b * Hq + blockIdx.y) * Tq + t) * DHq + tx*8;
        } else {
            op = out + (size_t)m * Cq + bn + tx*8;
        }
        *(float4*)op       = make_float4(r[0], r[1], r[2], r[3]);
        *(float4*)(op + 4) = make_float4(r[4], r[5], r[6], r[7]);
    }
}

__global__ __launch_bounds__(256, 2)
void qkv_gemm_kernel(const float* __restrict__ x,
                     const float* __restrict__ Wqp,
                     const float* __restrict__ Wkp,
                     const float* __restrict__ Wvp)
{
    const float* W = (blockIdx.z == 0) ? Wqp : (blockIdx.z == 1) ? Wkp : Wvp;
    float* out     = (blockIdx.z == 0) ? g_q : (blockIdx.z == 1) ? g_k : g_v;
    gemm_body<true>(x, W, out, blockIdx.z < 2);
}

__global__ __launch_bounds__(256, 2)
void final_gemm_kernel(const float* __restrict__ Wo, float* __restrict__ out)
{
    gemm_body<false>(g_att, Wo, out, false);
}

// ---------------------------------------------------------------------------
// Zero kv / ksum accumulators (graph replays must be deterministic)
// ---------------------------------------------------------------------------
__global__ void zero_kv_kernel()
{
    const int idx = blockIdx.x * blockDim.x + threadIdx.x;
    if (idx < Bq*Hq*DHq*DHq) g_kv[idx] = 0.f;
    if (idx < Bq*Hq*DHq)     g_ksum[idx] = 0.f;
}

// ---------------------------------------------------------------------------
// kv[bh][d][e] = sum_t k[bh][t][d] * v[bh][t][e];  ksum[bh][d] = sum_t k
// grid (64, 8): each block reduces 512 t-rows, atomicAdd finalize.
// ---------------------------------------------------------------------------
__global__ __launch_bounds__(256, 2)
void kv_kernel()
{
    const int bh = blockIdx.x;
    const int t0 = blockIdx.y * 512;
    const float* K = g_k + (size_t)bh * Tq * DHq;
    const float* V = g_v + (size_t)bh * Tq * DHq;

    __shared__ float ks[16][128];
    __shared__ float vs[16][128];
    const int tid  = threadIdx.x;
    const int tx   = tid & 15;
    const int ty   = tid >> 4;
    const int lrow = tid >> 4;          // 0..15
    const int lcol = (tid & 15) * 8;    // 0..120
    const int d     = tid & 127;
    const int thalf = tid >> 7;         // 0/1

    float acc[8][8];
    #pragma unroll
    for (int i = 0; i < 8; i++)
        #pragma unroll
        for (int j = 0; j < 8; j++) acc[i][j] = 0.f;
    float lsum = 0.f;

    for (int tc = 0; tc < 512; tc += 16) {
        const float* kp = K + (size_t)(t0 + tc + lrow) * DHq + lcol;
        const float* vp = V + (size_t)(t0 + tc + lrow) * DHq + lcol;
        *(float4*)&ks[lrow][lcol]     = *(const float4*)kp;
        *(float4*)&ks[lrow][lcol + 4] = *(const float4*)(kp + 4);
        *(float4*)&vs[lrow][lcol]     = *(const float4*)vp;
        *(float4*)&vs[lrow][lcol + 4] = *(const float4*)(vp + 4);
        __syncthreads();
        #pragma unroll
        for (int tt = 0; tt < 16; tt++) {
            float kf[8], vf[8];
            *(float4*)&kf[0] = *(const float4*)&ks[tt][ty*8];
            *(float4*)&kf[4] = *(const float4*)&ks[tt][ty*8+4];
            *(float4*)&vf[0] = *(const float4*)&vs[tt][tx*8];
            *(float4*)&vf[4] = *(const float4*)&vs[tt][tx*8+4];
            #pragma unroll
            for (int i = 0; i < 8; i++)
                #pragma unroll
                for (int j = 0; j < 8; j++)
                    acc[i][j] += kf[i] * vf[j];
        }
        #pragma unroll
        for (int tt = thalf; tt < 16; tt += 2) lsum += ks[tt][d];
        __syncthreads();
    }

    float* kvp = g_kv + (size_t)bh * DHq * DHq;
    #pragma unroll
    for (int i = 0; i < 8; i++)
        #pragma unroll
        for (int j = 0; j < 8; j++)
            atomicAdd(&kvp[(ty*8 + i) * DHq + tx*8 + j], acc[i][j]);
    atomicAdd(&g_ksum[bh * DHq + d], lsum);
}

// ---------------------------------------------------------------------------
// o[b,t,h*Dh+e] = z(t) * sum_d q[bh][t][d] * kv[bh][d][e]
// z(t) = 1/(q[t].ksum + 1e-6).  grid (64, T/32), 256 thr, dyn smem ~80.6 KB.
// ---------------------------------------------------------------------------
__global__ __launch_bounds__(256)
void attn_out_kernel()
{
    extern __shared__ float sm[];
    float* kvs = sm;             // 16384
    float* kss = sm + 16384;     // 128
    float* qs  = kss + 128;      // 4096
    float* zs  = qs + 4096;      // 32

    const int bh   = blockIdx.x;
    const int t0   = blockIdx.y * 32;
    const int tid  = threadIdx.x;
    const int warp = tid >> 5;
    const int lane = tid & 31;

    const float4* kvg = (const float4*)(g_kv + (size_t)bh * DHq * DHq);
    for (int i = tid; i < 4096; i += 256) ((float4*)kvs)[i] = kvg[i];
    if (tid < 32) ((float4*)kss)[tid] = ((const float4*)(g_ksum + bh * DHq))[tid];
    const float4* qg = (const float4*)(g_q + ((size_t)bh * Tq + t0) * DHq);
    for (int i = tid; i < 1024; i += 256) ((float4*)qs)[i] = qg[i];
    __syncthreads();

    // z normalizer: warp w handles t = w*4+s
    #pragma unroll
    for (int s = 0; s < 4; s++) {
        const int t = warp * 4 + s;
        float p = 0.f;
        #pragma unroll
        for (int dd = lane; dd < 128; dd += 32) p += qs[t*128 + dd] * kss[dd];
        p += __shfl_xor_sync(0xffffffffu, p, 16);
        p += __shfl_xor_sync(0xffffffffu, p, 8);
        p += __shfl_xor_sync(0xffffffffu, p, 4);
        p += __shfl_xor_sync(0xffffffffu, p, 2);
        p += __shfl_xor_sync(0xffffffffu, p, 1);
        if (lane == 0) zs[t] = 1.f / (p + 1e-6f);
    }
    __syncthreads();

    const int b = bh >> 4;
    const int h = bh & 15;
    for (int s = 0; s < 4; s++) {
        const int t = warp * 4 + s;
        const float* qr = qs + t * 128;
        float4 a = make_float4(0.f, 0.f, 0.f, 0.f);
        #pragma unroll 8
        for (int dd = 0; dd < 128; dd++) {
            const float qd = qr[dd];
            const float4 kvv = *(const float4*)&kvs[dd*128 + lane*4];
            a.x += qd * kvv.x; a.y += qd * kvv.y;
            a.z += qd * kvv.z; a.w += qd * kvv.w;
        }
        const float z = zs[t];
        a.x *= z; a.y *= z; a.z *= z; a.w *= z;
        *(float4*)(g_att + ((size_t)(b * Tq) + t0 + t) * Cq + h * DHq + lane * 4) = a;
    }
}

// ---------------------------------------------------------------------------
extern "C" void kernel_launch(void* const* d_in, const int* in_sizes, int n_in,
                              void* d_out, int out_size)
{
    const float* x  = (const float*)d_in[0];
    // d_in[1] = cos, d_in[2] = sin : unused by the reference module
    const float* Wq = (const float*)d_in[3];
    const float* Wk = (const float*)d_in[4];
    const float* Wv = (const float*)d_in[5];
    const float* Wo = (const float*)d_in[6];
    float* out = (float*)d_out;

    cudaFuncSetAttribute(attn_out_kernel,
                         cudaFuncAttributeMaxDynamicSharedMemorySize, 82560);

    qkv_gemm_kernel<<<dim3(Mq/128, Cq/128, 3), 256>>>(x, Wq, Wk, Wv);
    zero_kv_kernel<<<(Bq*Hq*DHq*DHq + 255)/256, 256>>>();
    kv_kernel<<<dim3(Bq*Hq, Tq/512), 256>>>();
    attn_out_kernel<<<dim3(Bq*Hq, Tq/32), 256, 82560>>>();
    final_gemm_kernel<<<dim3(Mq/128, Cq/128), 256>>>(Wo, out);
}

// round 3
// speedup vs baseline: 1.8674x; 1.8674x over previous
#include <cuda_runtime.h>
#include <cuda_fp16.h>
#include <cstdint>

// Problem constants
#define Bq   4
#define Tq   4096
#define Cq   2048
#define Hq   16
#define DHq  128
#define Mq   (Bq*Tq)          // 16384

// Scratch (device globals: allocation-free rule)
__device__ float g_q[Mq*Cq];      // [B,H,T,Dh]
__device__ float g_k[Mq*Cq];      // [B,H,T,Dh]
__device__ float g_v[Mq*Cq];      // [B,H,T,Dh]
__device__ float g_att[Mq*Cq];    // [B,T,C]
__device__ float g_kv[Bq*Hq*DHq*DHq];
__device__ float g_ksum[Bq*Hq*DHq];

__device__ __forceinline__ float featmap(float y) {
    return y > 0.f ? y + 1.f : __expf(y);   // elu(y)+1
}

// ===========================================================================
// fp16 3-product (hi/lo split) tensor-core GEMM via mma.sync (sm_80+ path,
// legal under compute_100 — tcgen05 is NOT available in this toolchain).
// C[m,n] = sum_k A[m,k] * W[n,k]   (NT)
// CTA tile 128x128, BK=32, 8 warps (4m x 2n), warp tile 32x64.
// ===========================================================================
#define BKh          32
#define PITCHh       40                    // halves per smem row (conflict-free)
#define TILE_HALVES  (128*PITCHh)          // 5120
#define STAGE_HALVES (4*TILE_HALVES)       // Ah|Al|Bh|Bl = 20480
#define GEMM_SMEM    (2*STAGE_HALVES*2)    // 81920 bytes

__device__ __forceinline__ void mma16816(float* d, const uint32_t* a, const uint32_t* b)
{
    asm volatile(
        "mma.sync.aligned.m16n8k16.row.col.f32.f16.f16.f32 "
        "{%0,%1,%2,%3}, {%4,%5,%6,%7}, {%8,%9}, {%0,%1,%2,%3};"
        : "+f"(d[0]), "+f"(d[1]), "+f"(d[2]), "+f"(d[3])
        : "r"(a[0]), "r"(a[1]), "r"(a[2]), "r"(a[3]), "r"(b[0]), "r"(b[1]));
}

template<int QKVLAY>
__device__ __forceinline__ void mma_gemm(const float* __restrict__ A,
                                         const float* __restrict__ W,
                                         float* __restrict__ out,
                                         bool act)
{
    extern __shared__ __half sh[];
    const int tid  = threadIdx.x;
    const int bn   = blockIdx.x * 128;   // N-dim outer (16 blocks) -> A tiles reused in L2
    const int bm   = blockIdx.y * 128;

    // loader mapping: row = tid>>1 (0..127), 16 consecutive floats at (tid&1)*16
    const int lr = tid >> 1;
    const int lc = (tid & 1) * 16;
    const float* ag = A + (size_t)(bm + lr) * Cq + lc;
    const float* bg = W + (size_t)(bn + lr) * Cq + lc;

    float ra[16], rb[16];
    #pragma unroll
    for (int q = 0; q < 4; q++) {
        *(float4*)&ra[q*4] = *(const float4*)(ag + q*4);
        *(float4*)&rb[q*4] = *(const float4*)(bg + q*4);
    }

    const int wid  = tid >> 5;
    const int lane = tid & 31;
    const int wm   = (wid & 3) * 32;     // warp rows
    const int wn   = (wid >> 2) * 64;    // warp cols
    const int r0   = lane >> 2;
    const int c0   = (lane & 3) * 2;

    float acc[2][8][4];
    #pragma unroll
    for (int i = 0; i < 2; i++)
        #pragma unroll
        for (int j = 0; j < 8; j++)
            #pragma unroll
            for (int e = 0; e < 4; e++) acc[i][j][e] = 0.f;

    const int NCHUNK = Cq / BKh;  // 64

    for (int kc = 0; kc < NCHUNK; kc++) {
        __half* st = sh + (kc & 1) * STAGE_HALVES;
        __half* Ah = st;
        __half* Al = st + TILE_HALVES;
        __half* Bh = st + 2*TILE_HALVES;
        __half* Bl = st + 3*TILE_HALVES;

        // hi/lo split + store
        #pragma unroll
        for (int q = 0; q < 4; q++) {
            const int off = lr * PITCHh + lc + q*4;
            #pragma unroll
            for (int p = 0; p < 2; p++) {
                float v0 = ra[q*4 + p*2], v1 = ra[q*4 + p*2 + 1];
                __half2 h  = __floats2half2_rn(v0, v1);
                float2 bk  = __half22float2(h);
                __half2 l  = __floats2half2_rn(v0 - bk.x, v1 - bk.y);
                *(__half2*)&Ah[off + p*2] = h;
                *(__half2*)&Al[off + p*2] = l;
                float w0 = rb[q*4 + p*2], w1 = rb[q*4 + p*2 + 1];
                __half2 h2 = __floats2half2_rn(w0, w1);
                float2 bk2 = __half22float2(h2);
                __half2 l2 = __floats2half2_rn(w0 - bk2.x, w1 - bk2.y);
                *(__half2*)&Bh[off + p*2] = h2;
                *(__half2*)&Bl[off + p*2] = l2;
            }
        }
        __syncthreads();

        // prefetch next chunk
        if (kc + 1 < NCHUNK) {
            const float* a2 = ag + (kc + 1) * BKh;
            const float* b2 = bg + (kc + 1) * BKh;
            #pragma unroll
            for (int q = 0; q < 4; q++) {
                *(float4*)&ra[q*4] = *(const float4*)(a2 + q*4);
                *(float4*)&rb[q*4] = *(const float4*)(b2 + q*4);
            }
        }

        // compute: two k16 steps
        #pragma unroll
        for (int ks = 0; ks < 2; ks++) {
            const int k0 = ks * 16;
            uint32_t AHf[2][4], ALf[2][4];
            #pragma unroll
            for (int mt = 0; mt < 2; mt++) {
                const int rb0 = wm + mt*16;
                AHf[mt][0] = *(uint32_t*)&Ah[(rb0 + r0    ) * PITCHh + k0 + c0    ];
                AHf[mt][1] = *(uint32_t*)&Ah[(rb0 + r0 + 8) * PITCHh + k0 + c0    ];
                AHf[mt][2] = *(uint32_t*)&Ah[(rb0 + r0    ) * PITCHh + k0 + c0 + 8];
                AHf[mt][3] = *(uint32_t*)&Ah[(rb0 + r0 + 8) * PITCHh + k0 + c0 + 8];
                ALf[mt][0] = *(uint32_t*)&Al[(rb0 + r0    ) * PITCHh + k0 + c0    ];
                ALf[mt][1] = *(uint32_t*)&Al[(rb0 + r0 + 8) * PITCHh + k0 + c0    ];
                ALf[mt][2] = *(uint32_t*)&Al[(rb0 + r0    ) * PITCHh + k0 + c0 + 8];
                ALf[mt][3] = *(uint32_t*)&Al[(rb0 + r0 + 8) * PITCHh + k0 + c0 + 8];
            }
            #pragma unroll
            for (int nt = 0; nt < 8; nt++) {
                const int nb = wn + nt*8 + r0;
                uint32_t BHf[2], BLf[2];
                BHf[0] = *(uint32_t*)&Bh[nb * PITCHh + k0 + c0    ];
                BHf[1] = *(uint32_t*)&Bh[nb * PITCHh + k0 + c0 + 8];
                BLf[0] = *(uint32_t*)&Bl[nb * PITCHh + k0 + c0    ];
                BLf[1] = *(uint32_t*)&Bl[nb * PITCHh + k0 + c0 + 8];
                #pragma unroll
                for (int mt = 0; mt < 2; mt++) {
                    mma16816(acc[mt][nt], AHf[mt], BHf);
                    mma16816(acc[mt][nt], AHf[mt], BLf);
                    mma16816(acc[mt][nt], ALf[mt], BHf);
                }
            }
        }
        __syncthreads();
    }

    // epilogue: thread holds rows (wm+mt*16+r0, +8), cols wn+nt*8+c0 (+1)
    #pragma unroll
    for (int mt = 0; mt < 2; mt++) {
        #pragma unroll
        for (int half = 0; half < 2; half++) {
            const int m = bm + wm + mt*16 + r0 + half*8;
            float* op;
            if (QKVLAY) {
                const int b = m >> 12;
                const int t = m & (Tq - 1);
                // h == blockIdx.x (since bn covers exactly one head of 128)
                op = out + (((size_t)b * Hq + blockIdx.x) * Tq + t) * DHq;
            } else {
                op = out + (size_t)m * Cq + bn;
            }
            #pragma unroll
            for (int nt = 0; nt < 8; nt++) {
                float v0 = acc[mt][nt][half*2];
                float v1 = acc[mt][nt][half*2 + 1];
                if (act) { v0 = featmap(v0); v1 = featmap(v1); }
                *(float2*)(op + wn + nt*8 + c0) = make_float2(v0, v1);
            }
        }
    }
}

__global__ __launch_bounds__(256)
void qkv_mma_kernel(const float* __restrict__ x,
                    const float* __restrict__ Wqp,
                    const float* __restrict__ Wkp,
                    const float* __restrict__ Wvp)
{
    const float* W = (blockIdx.z == 0) ? Wqp : (blockIdx.z == 1) ? Wkp : Wvp;
    float* o       = (blockIdx.z == 0) ? g_q : (blockIdx.z == 1) ? g_k : g_v;
    mma_gemm<1>(x, W, o, blockIdx.z < 2);
}

__global__ __launch_bounds__(256)
void out_mma_kernel(const float* __restrict__ Wo, float* __restrict__ out)
{
    mma_gemm<0>(g_att, Wo, out, false);
}

// ---------------------------------------------------------------------------
// Zero kv / ksum accumulators
// ---------------------------------------------------------------------------
__global__ void zero_kv_kernel()
{
    const int idx = blockIdx.x * blockDim.x + threadIdx.x;
    if (idx < Bq*Hq*DHq*DHq) g_kv[idx] = 0.f;
    if (idx < Bq*Hq*DHq)     g_ksum[idx] = 0.f;
}

// ---------------------------------------------------------------------------
// kv[bh][d][e] = sum_t k[bh][t][d] * v[bh][t][e];  ksum[bh][d] = sum_t k
// ---------------------------------------------------------------------------
__global__ __launch_bounds__(256, 2)
void kv_kernel()
{
    const int bh = blockIdx.x;
    const int t0 = blockIdx.y * 512;
    const float* K = g_k + (size_t)bh * Tq * DHq;
    const float* V = g_v + (size_t)bh * Tq * DHq;

    __shared__ float ks[16][128];
    __shared__ float vs[16][128];
    const int tid  = threadIdx.x;
    const int tx   = tid & 15;
    const int ty   = tid >> 4;
    const int lrow = tid >> 4;
    const int lcol = (tid & 15) * 8;
    const int d     = tid & 127;
    const int thalf = tid >> 7;

    float acc[8][8];
    #pragma unroll
    for (int i = 0; i < 8; i++)
        #pragma unroll
        for (int j = 0; j < 8; j++) acc[i][j] = 0.f;
    float lsum = 0.f;

    for (int tc = 0; tc < 512; tc += 16) {
        const float* kp = K + (size_t)(t0 + tc + lrow) * DHq + lcol;
        const float* vp = V + (size_t)(t0 + tc + lrow) * DHq + lcol;
        *(float4*)&ks[lrow][lcol]     = *(const float4*)kp;
        *(float4*)&ks[lrow][lcol + 4] = *(const float4*)(kp + 4);
        *(float4*)&vs[lrow][lcol]     = *(const float4*)vp;
        *(float4*)&vs[lrow][lcol + 4] = *(const float4*)(vp + 4);
        __syncthreads();
        #pragma unroll
        for (int tt = 0; tt < 16; tt++) {
            float kf[8], vf[8];
            *(float4*)&kf[0] = *(const float4*)&ks[tt][ty*8];
            *(float4*)&kf[4] = *(const float4*)&ks[tt][ty*8+4];
            *(float4*)&vf[0] = *(const float4*)&vs[tt][tx*8];
            *(float4*)&vf[4] = *(const float4*)&vs[tt][tx*8+4];
            #pragma unroll
            for (int i = 0; i < 8; i++)
                #pragma unroll
                for (int j = 0; j < 8; j++)
                    acc[i][j] += kf[i] * vf[j];
        }
        #pragma unroll
        for (int tt = thalf; tt < 16; tt += 2) lsum += ks[tt][d];
        __syncthreads();
    }

    float* kvp = g_kv + (size_t)bh * DHq * DHq;
    #pragma unroll
    for (int i = 0; i < 8; i++)
        #pragma unroll
        for (int j = 0; j < 8; j++)
            atomicAdd(&kvp[(ty*8 + i) * DHq + tx*8 + j], acc[i][j]);
    atomicAdd(&g_ksum[bh * DHq + d], lsum);
}

// ---------------------------------------------------------------------------
// o[b,t,h*Dh+e] = z(t) * sum_d q[bh][t][d] * kv[bh][d][e]
// ---------------------------------------------------------------------------
__global__ __launch_bounds__(256)
void attn_out_kernel()
{
    extern __shared__ float sm[];
    float* kvs = sm;
    float* kss = sm + 16384;
    float* qs  = kss + 128;
    float* zs  = qs + 4096;

    const int bh   = blockIdx.x;
    const int t0   = blockIdx.y * 32;
    const int tid  = threadIdx.x;
    const int warp = tid >> 5;
    const int lane = tid & 31;

    const float4* kvg = (const float4*)(g_kv + (size_t)bh * DHq * DHq);
    for (int i = tid; i < 4096; i += 256) ((float4*)kvs)[i] = kvg[i];
    if (tid < 32) ((float4*)kss)[tid] = ((const float4*)(g_ksum + bh * DHq))[tid];
    const float4* qg = (const float4*)(g_q + ((size_t)bh * Tq + t0) * DHq);
    for (int i = tid; i < 1024; i += 256) ((float4*)qs)[i] = qg[i];
    __syncthreads();

    #pragma unroll
    for (int s = 0; s < 4; s++) {
        const int t = warp * 4 + s;
        float p = 0.f;
        #pragma unroll
        for (int dd = lane; dd < 128; dd += 32) p += qs[t*128 + dd] * kss[dd];
        p += __shfl_xor_sync(0xffffffffu, p, 16);
        p += __shfl_xor_sync(0xffffffffu, p, 8);
        p += __shfl_xor_sync(0xffffffffu, p, 4);
        p += __shfl_xor_sync(0xffffffffu, p, 2);
        p += __shfl_xor_sync(0xffffffffu, p, 1);
        if (lane == 0) zs[t] = 1.f / (p + 1e-6f);
    }
    __syncthreads();

    const int b = bh >> 4;
    const int h = bh & 15;
    for (int s = 0; s < 4; s++) {
        const int t = warp * 4 + s;
        const float* qr = qs + t * 128;
        float4 a = make_float4(0.f, 0.f, 0.f, 0.f);
        #pragma unroll 8
        for (int dd = 0; dd < 128; dd++) {
            const float qd = qr[dd];
            const float4 kvv = *(const float4*)&kvs[dd*128 + lane*4];
            a.x += qd * kvv.x; a.y += qd * kvv.y;
            a.z += qd * kvv.z; a.w += qd * kvv.w;
        }
        const float z = zs[t];
        a.x *= z; a.y *= z; a.z *= z; a.w *= z;
        *(float4*)(g_att + ((size_t)(b * Tq) + t0 + t) * Cq + h * DHq + lane * 4) = a;
    }
}

// ---------------------------------------------------------------------------
extern "C" void kernel_launch(void* const* d_in, const int* in_sizes, int n_in,
                              void* d_out, int out_size)
{
    const float* x  = (const float*)d_in[0];
    // d_in[1] = cos, d_in[2] = sin : unused by the reference module
    const float* Wq = (const float*)d_in[3];
    const float* Wk = (const float*)d_in[4];
    const float* Wv = (const float*)d_in[5];
    const float* Wo = (const float*)d_in[6];
    float* out = (float*)d_out;

    cudaFuncSetAttribute(qkv_mma_kernel,
                         cudaFuncAttributeMaxDynamicSharedMemorySize, GEMM_SMEM);
    cudaFuncSetAttribute(out_mma_kernel,
                         cudaFuncAttributeMaxDynamicSharedMemorySize, GEMM_SMEM);
    cudaFuncSetAttribute(attn_out_kernel,
                         cudaFuncAttributeMaxDynamicSharedMemorySize, 82560);

    // grid.x = N-blocks (16) so consecutive CTAs reuse the same A tile via L2
    qkv_mma_kernel<<<dim3(Cq/128, Mq/128, 3), 256, GEMM_SMEM>>>(x, Wq, Wk, Wv);
    zero_kv_kernel<<<(Bq*Hq*DHq*DHq + 255)/256, 256>>>();
    kv_kernel<<<dim3(Bq*Hq, Tq/512), 256>>>();
    attn_out_kernel<<<dim3(Bq*Hq, Tq/32), 256, 82560>>>();
    out_mma_kernel<<<dim3(Cq/128, Mq/128), 256, GEMM_SMEM>>>(Wo, out);
}

// round 6
// speedup vs baseline: 2.7045x; 1.4482x over previous
#include <cuda_runtime.h>
#include <cuda_fp16.h>
#include <cstdint>

// Problem constants
#define Bq   4
#define Tq   4096
#define Cq   2048
#define Hq   16
#define DHq  128
#define Mq   (Bq*Tq)          // 16384

// Scratch (device globals: allocation-free rule)
__device__ float g_q[Mq*Cq];      // [B,H,T,Dh] fp32 (attn_out input)
__device__ float g_k[Mq*Cq];      // [B,H,T,Dh]
__device__ float g_v[Mq*Cq];      // [B,H,T,Dh]
__device__ float g_kv[Bq*Hq*DHq*DHq];
__device__ float g_ksum[Bq*Hq*DHq];

// hi/lo fp16 split operands (pre-converted once per launch)
__device__ __half g_xh[Mq*Cq];
__device__ __half g_xl[Mq*Cq];
__device__ __half g_wh[4*Cq*Cq];   // Wq|Wk|Wv|Wo
__device__ __half g_wl[4*Cq*Cq];
__device__ __half g_ath[Mq*Cq];    // attention output [B,T,C] hi
__device__ __half g_atl[Mq*Cq];    // lo

__device__ __forceinline__ float featmap(float y) {
    return y > 0.f ? y + 1.f : __expf(y);   // elu(y)+1
}

__device__ __forceinline__ uint32_t smem_u32(const void* p) {
    uint32_t a;
    asm("{ .reg .u64 t; cvta.to.shared.u64 t, %1; cvt.u32.u64 %0, t; }"
        : "=r"(a) : "l"(p));
    return a;
}

__device__ __forceinline__ void cpa16(uint32_t s, const void* g) {
    asm volatile("cp.async.cg.shared.global [%0], [%1], 16;" :: "r"(s), "l"(g));
}

#define LDSM4(r, a)                                                            \
    asm volatile("ldmatrix.sync.aligned.m8n8.x4.shared.b16 {%0,%1,%2,%3}, [%4];" \
        : "=r"((r)[0]), "=r"((r)[1]), "=r"((r)[2]), "=r"((r)[3]) : "r"(a))

__device__ __forceinline__ void mma16816(float* d, const uint32_t* a, const uint32_t* b)
{
    asm volatile(
        "mma.sync.aligned.m16n8k16.row.col.f32.f16.f16.f32 "
        "{%0,%1,%2,%3}, {%4,%5,%6,%7}, {%8,%9}, {%0,%1,%2,%3};"
        : "+f"(d[0]), "+f"(d[1]), "+f"(d[2]), "+f"(d[3])
        : "r"(a[0]), "r"(a[1]), "r"(a[2]), "r"(a[3]), "r"(b[0]), "r"(b[1]));
}

// ===========================================================================
// fp32 -> (hi fp16, lo fp16) split, elementwise.
// dst_sel: 0 = x, 1..4 = Wq/Wk/Wv/Wo
// ===========================================================================
__global__ void cvt_kernel(const float* __restrict__ src, int dst_sel, int n4)
{
    const int i = blockIdx.x * blockDim.x + threadIdx.x;
    if (i >= n4) return;
    __half *hi, *lo;
    if (dst_sel == 0) { hi = g_xh; lo = g_xl; }
    else {
        hi = g_wh + (size_t)(dst_sel - 1) * Cq * Cq;
        lo = g_wl + (size_t)(dst_sel - 1) * Cq * Cq;
    }
    float4 v = ((const float4*)src)[i];
    __half2 h0 = __floats2half2_rn(v.x, v.y);
    float2  b0 = __half22float2(h0);
    __half2 l0 = __floats2half2_rn(v.x - b0.x, v.y - b0.y);
    __half2 h1 = __floats2half2_rn(v.z, v.w);
    float2  b1 = __half22float2(h1);
    __half2 l1 = __floats2half2_rn(v.z - b1.x, v.w - b1.y);
    ((__half2*)hi)[i*2]   = h0;  ((__half2*)hi)[i*2+1] = h1;
    ((__half2*)lo)[i*2]   = l0;  ((__half2*)lo)[i*2+1] = l1;
}

// ===========================================================================
// 3-product fp16 GEMM v2: cp.async 3-stage pipeline + ldmatrix fragments.
// C[m,n] = sum_k A[m,k]*B[n,k]; A,B pre-split hi/lo halves, K-major (2048).
// CTA 128x128, BK=32 halves. SMEM rows: 32 halves (64B), XOR swizzle:
//   sw(off) = off ^ (((off>>7)&3)<<4)   -> conflict-free LDSM.
// Stage = Ah|Al|Bh|Bl tiles, 4 x 8KB = 32KB; 3 stages = 96KB.
// ===========================================================================
#define NST          3
#define STG_BYTES    32768
#define GEMM_SMEM    (NST*STG_BYTES)      // 98304

template<int QKVLAY>
__device__ __forceinline__ void mma_gemm2(const __half* __restrict__ Ah_g,
                                          const __half* __restrict__ Al_g,
                                          const __half* __restrict__ Bh_g,
                                          const __half* __restrict__ Bl_g,
                                          float* __restrict__ out, bool act)
{
    extern __shared__ char sm2[];
    const uint32_t sb = smem_u32(sm2);
    const int tid = threadIdx.x;
    const int bn  = blockIdx.x * 128;    // N outer -> A-tile L2 reuse
    const int bm  = blockIdx.y * 128;

    // ---- cp.async mapping: row = tid>>1, two 16B segs at (tid&1)*2 ----
    const int rowG = tid >> 1;
    const int seg0 = (tid & 1) * 2;
    const uint32_t xrg = ((rowG >> 1) & 3) << 4;
    const uint32_t d0 = rowG*64 + (( seg0   *16) ^ xrg);
    const uint32_t d1 = rowG*64 + (((seg0+1)*16) ^ xrg);
    const __half* sAh = Ah_g + (size_t)(bm + rowG) * Cq + seg0*8;
    const __half* sAl = Al_g + (size_t)(bm + rowG) * Cq + seg0*8;
    const __half* sBh = Bh_g + (size_t)(bn + rowG) * Cq + seg0*8;
    const __half* sBl = Bl_g + (size_t)(bn + rowG) * Cq + seg0*8;

    auto issue = [&](int kc, int slot) {
        const uint32_t b = sb + slot * STG_BYTES;
        const int ko = kc * 32;
        cpa16(b         + d0, sAh + ko);  cpa16(b         + d1, sAh + ko + 8);
        cpa16(b +  8192 + d0, sAl + ko);  cpa16(b +  8192 + d1, sAl + ko + 8);
        cpa16(b + 16384 + d0, sBh + ko);  cpa16(b + 16384 + d1, sBh + ko + 8);
        cpa16(b + 24576 + d0, sBl + ko);  cpa16(b + 24576 + d1, sBl + ko + 8);
        asm volatile("cp.async.commit_group;" ::: "memory");
    };

    issue(0, 0);
    issue(1, 1);

    // ---- fragment mapping ----
    const int wid  = tid >> 5;
    const int lane = tid & 31;
    const int wm = (wid & 3) * 32;
    const int wn = (wid >> 2) * 64;
    const uint32_t xs  = ((lane >> 1) & 3) << 4;
    const uint32_t kqa = (lane >> 4) * 16;          // A: lanes 0-15 k0, 16-31 k+8
    const uint32_t kqb = ((lane >> 3) & 1) * 16;    // B: groups alternate k
    uint32_t saofs[2], sbofs[4];
    #pragma unroll
    for (int mt = 0; mt < 2; mt++)
        saofs[mt] = (uint32_t)(wm + mt*16 + (lane & 15)) * 64;
    #pragma unroll
    for (int p = 0; p < 4; p++)
        sbofs[p] = (uint32_t)(wn + p*16 + ((lane >> 4) & 1)*8 + (lane & 7)) * 64;

    float acc[2][8][4];
    #pragma unroll
    for (int i = 0; i < 2; i++)
        #pragma unroll
        for (int j = 0; j < 8; j++)
            #pragma unroll
            for (int e = 0; e < 4; e++) acc[i][j][e] = 0.f;

    const int NCHUNK = Cq / 32;   // 64

    for (int kc = 0; kc < NCHUNK; kc++) {
        if (kc == NCHUNK - 1) asm volatile("cp.async.wait_group 0;" ::: "memory");
        else                  asm volatile("cp.async.wait_group 1;" ::: "memory");
        __syncthreads();
        if (kc + 2 < NCHUNK) issue(kc + 2, (kc + 2) % NST);

        const uint32_t st = sb + (kc % NST) * STG_BYTES;
        #pragma unroll
        for (int ks = 0; ks < 2; ks++) {
            uint32_t ah[2][4], al[2][4];
            const uint32_t ca = (ks*32 + kqa) ^ xs;
            #pragma unroll
            for (int mt = 0; mt < 2; mt++) {
                LDSM4(ah[mt], st +         saofs[mt] + ca);
                LDSM4(al[mt], st +  8192 + saofs[mt] + ca);
            }
            const uint32_t cb = (ks*32 + kqb) ^ xs;
            #pragma unroll
            for (int p = 0; p < 4; p++) {
                uint32_t bh[4], bl[4];
                LDSM4(bh, st + 16384 + sbofs[p] + cb);
                LDSM4(bl, st + 24576 + sbofs[p] + cb);
                #pragma unroll
                for (int mt = 0; mt < 2; mt++) {
                    mma16816(acc[mt][2*p],   ah[mt], bh);
                    mma16816(acc[mt][2*p],   ah[mt], bl);
                    mma16816(acc[mt][2*p],   al[mt], bh);
                    mma16816(acc[mt][2*p+1], ah[mt], bh + 2);
                    mma16816(acc[mt][2*p+1], ah[mt], bl + 2);
                    mma16816(acc[mt][2*p+1], al[mt], bh + 2);
                }
            }
        }
    }

    // ---- epilogue (same mapping as r3, proven correct) ----
    const int r0 = lane >> 2;
    const int c0 = (lane & 3) * 2;
    #pragma unroll
    for (int mt = 0; mt < 2; mt++) {
        #pragma unroll
        for (int half = 0; half < 2; half++) {
            const int m = bm + wm + mt*16 + r0 + half*8;
            float* op;
            if (QKVLAY) {
                const int b = m >> 12;
                const int t = m & (Tq - 1);
                op = out + (((size_t)b * Hq + blockIdx.x) * Tq + t) * DHq;
            } else {
                op = out + (size_t)m * Cq + bn;
            }
            #pragma unroll
            for (int nt = 0; nt < 8; nt++) {
                float v0 = acc[mt][nt][half*2];
                float v1 = acc[mt][nt][half*2 + 1];
                if (act) { v0 = featmap(v0); v1 = featmap(v1); }
                *(float2*)(op + wn + nt*8 + c0) = make_float2(v0, v1);
            }
        }
    }
}

__global__ __launch_bounds__(256)
void qkv_mma_kernel()
{
    const int z = blockIdx.z;
    const __half* Bh = g_wh + (size_t)z * Cq * Cq;
    const __half* Bl = g_wl + (size_t)z * Cq * Cq;
    float* o = (z == 0) ? g_q : (z == 1) ? g_k : g_v;
    mma_gemm2<1>(g_xh, g_xl, Bh, Bl, o, z < 2);
}

__global__ __launch_bounds__(256)
void out_mma_kernel(float* __restrict__ out)
{
    mma_gemm2<0>(g_ath, g_atl,
                 g_wh + (size_t)3 * Cq * Cq, g_wl + (size_t)3 * Cq * Cq,
                 out, false);
}

// ---------------------------------------------------------------------------
// Zero kv / ksum accumulators
// ---------------------------------------------------------------------------
__global__ void zero_kv_kernel()
{
    const int idx = blockIdx.x * blockDim.x + threadIdx.x;
    if (idx < Bq*Hq*DHq*DHq) g_kv[idx] = 0.f;
    if (idx < Bq*Hq*DHq)     g_ksum[idx] = 0.f;
}

// ---------------------------------------------------------------------------
// kv[bh][d][e] = sum_t k[bh][t][d] * v[bh][t][e];  ksum[bh][d] = sum_t k
// ---------------------------------------------------------------------------
__global__ __launch_bounds__(256, 2)
void kv_kernel()
{
    const int bh = blockIdx.x;
    const int t0 = blockIdx.y * 512;
    const float* K = g_k + (size_t)bh * Tq * DHq;
    const float* V = g_v + (size_t)bh * Tq * DHq;

    __shared__ float ks[16][128];
    __shared__ float vs[16][128];
    const int tid  = threadIdx.x;
    const int tx   = tid & 15;
    const int ty   = tid >> 4;
    const int lrow = tid >> 4;
    const int lcol = (tid & 15) * 8;
    const int d     = tid & 127;
    const int thalf = tid >> 7;

    float acc[8][8];
    #pragma unroll
    for (int i = 0; i < 8; i++)
        #pragma unroll
        for (int j = 0; j < 8; j++) acc[i][j] = 0.f;
    float lsum = 0.f;

    for (int tc = 0; tc < 512; tc += 16) {
        const float* kp = K + (size_t)(t0 + tc + lrow) * DHq + lcol;
        const float* vp = V + (size_t)(t0 + tc + lrow) * DHq + lcol;
        *(float4*)&ks[lrow][lcol]     = *(const float4*)kp;
        *(float4*)&ks[lrow][lcol + 4] = *(const float4*)(kp + 4);
        *(float4*)&vs[lrow][lcol]     = *(const float4*)vp;
        *(float4*)&vs[lrow][lcol + 4] = *(const float4*)(vp + 4);
        __syncthreads();
        #pragma unroll
        for (int tt = 0; tt < 16; tt++) {
            float kf[8], vf[8];
            *(float4*)&kf[0] = *(const float4*)&ks[tt][ty*8];
            *(float4*)&kf[4] = *(const float4*)&ks[tt][ty*8+4];
            *(float4*)&vf[0] = *(const float4*)&vs[tt][tx*8];
            *(float4*)&vf[4] = *(const float4*)&vs[tt][tx*8+4];
            #pragma unroll
            for (int i = 0; i < 8; i++)
                #pragma unroll
                for (int j = 0; j < 8; j++)
                    acc[i][j] += kf[i] * vf[j];
        }
        #pragma unroll
        for (int tt = thalf; tt < 16; tt += 2) lsum += ks[tt][d];
        __syncthreads();
    }

    float* kvp = g_kv + (size_t)bh * DHq * DHq;
    #pragma unroll
    for (int i = 0; i < 8; i++)
        #pragma unroll
        for (int j = 0; j < 8; j++)
            atomicAdd(&kvp[(ty*8 + i) * DHq + tx*8 + j], acc[i][j]);
    atomicAdd(&g_ksum[bh * DHq + d], lsum);
}

// ---------------------------------------------------------------------------
// attn_out v2: 8 warps x 8 t-rows; kv re-read halved, q via float4 broadcast.
// Writes hi/lo halves directly (feeds out_mma).
// o[b,t,h*Dh+e] = z(t) * sum_d q[bh][t][d] * kv[bh][d][e]
// ---------------------------------------------------------------------------
#define ATT_SMEM ((16384 + 128 + 8192 + 64) * 4)   // 99072 bytes

__global__ __launch_bounds__(256)
void attn_out_kernel()
{
    extern __shared__ float sm[];
    float* kvs = sm;             // 16384
    float* kss = sm + 16384;     // 128
    float* qs  = kss + 128;      // 8192 (64 t x 128 d)
    float* zs  = qs + 8192;      // 64

    const int bh   = blockIdx.x;
    const int t0   = blockIdx.y * 64;
    const int tid  = threadIdx.x;
    const int warp = tid >> 5;
    const int lane = tid & 31;

    const float4* kvg = (const float4*)(g_kv + (size_t)bh * DHq * DHq);
    for (int i = tid; i < 4096; i += 256) ((float4*)kvs)[i] = kvg[i];
    if (tid < 32) ((float4*)kss)[tid] = ((const float4*)(g_ksum + bh * DHq))[tid];
    const float4* qg = (const float4*)(g_q + ((size_t)bh * Tq + t0) * DHq);
    for (int i = tid; i < 2048; i += 256) ((float4*)qs)[i] = qg[i];
    __syncthreads();

    #pragma unroll
    for (int s = 0; s < 8; s++) {
        const int t = warp * 8 + s;
        float p = 0.f;
        #pragma unroll
        for (int dd = lane; dd < 128; dd += 32) p += qs[t*128 + dd] * kss[dd];
        p += __shfl_xor_sync(0xffffffffu, p, 16);
        p += __shfl_xor_sync(0xffffffffu, p, 8);
        p += __shfl_xor_sync(0xffffffffu, p, 4);
        p += __shfl_xor_sync(0xffffffffu, p, 2);
        p += __shfl_xor_sync(0xffffffffu, p, 1);
        if (lane == 0) zs[t] = 1.f / (p + 1e-6f);
    }
    __syncthreads();

    float4 acc[8];
    #pragma unroll
    for (int s = 0; s < 8; s++) acc[s] = make_float4(0.f, 0.f, 0.f, 0.f);

    for (int dq = 0; dq < 32; dq++) {
        const float4 kv0 = *(const float4*)&kvs[(dq*4 + 0)*128 + lane*4];
        const float4 kv1 = *(const float4*)&kvs[(dq*4 + 1)*128 + lane*4];
        const float4 kv2 = *(const float4*)&kvs[(dq*4 + 2)*128 + lane*4];
        const float4 kv3 = *(const float4*)&kvs[(dq*4 + 3)*128 + lane*4];
        #pragma unroll
        for (int s = 0; s < 8; s++) {
            const float4 q4 = *(const float4*)&qs[(warp*8 + s)*128 + dq*4];
            acc[s].x += q4.x*kv0.x + q4.y*kv1.x + q4.z*kv2.x + q4.w*kv3.x;
            acc[s].y += q4.x*kv0.y + q4.y*kv1.y + q4.z*kv2.y + q4.w*kv3.y;
            acc[s].z += q4.x*kv0.z + q4.y*kv1.z + q4.z*kv2.z + q4.w*kv3.z;
            acc[s].w += q4.x*kv0.w + q4.y*kv1.w + q4.z*kv2.w + q4.w*kv3.w;
        }
    }

    const int b = bh >> 4;
    const int h = bh & 15;
    #pragma unroll
    for (int s = 0; s < 8; s++) {
        const int t = warp * 8 + s;
        const float z = zs[t];
        float4 a = acc[s];
        a.x *= z; a.y *= z; a.z *= z; a.w *= z;
        const size_t off = ((size_t)(b * Tq) + t0 + t) * Cq + h * DHq + lane * 4;
        __half2 h0 = __floats2half2_rn(a.x, a.y);
        float2  f0 = __half22float2(h0);
        __half2 l0 = __floats2half2_rn(a.x - f0.x, a.y - f0.y);
        __half2 h1 = __floats2half2_rn(a.z, a.w);
        float2  f1 = __half22float2(h1);
        __half2 l1 = __floats2half2_rn(a.z - f1.x, a.w - f1.y);
        *(__half2*)&g_ath[off]     = h0;
        *(__half2*)&g_ath[off + 2] = h1;
        *(__half2*)&g_atl[off]     = l0;
        *(__half2*)&g_atl[off + 2] = l1;
    }
}

// ---------------------------------------------------------------------------
extern "C" void kernel_launch(void* const* d_in, const int* in_sizes, int n_in,
                              void* d_out, int out_size)
{
    const float* x  = (const float*)d_in[0];
    // d_in[1] = cos, d_in[2] = sin : unused by the reference module
    const float* Wq = (const float*)d_in[3];
    const float* Wk = (const float*)d_in[4];
    const float* Wv = (const float*)d_in[5];
    const float* Wo = (const float*)d_in[6];
    float* out = (float*)d_out;

    cudaFuncSetAttribute(qkv_mma_kernel,
                         cudaFuncAttributeMaxDynamicSharedMemorySize, GEMM_SMEM);
    cudaFuncSetAttribute(out_mma_kernel,
                         cudaFuncAttributeMaxDynamicSharedMemorySize, GEMM_SMEM);
    cudaFuncSetAttribute(attn_out_kernel,
                         cudaFuncAttributeMaxDynamicSharedMemorySize, ATT_SMEM);

    // hi/lo pre-split
    cvt_kernel<<<(Mq*Cq/4 + 255)/256, 256>>>(x,  0, Mq*Cq/4);
    cvt_kernel<<<(Cq*Cq/4 + 255)/256, 256>>>(Wq, 1, Cq*Cq/4);
    cvt_kernel<<<(Cq*Cq/4 + 255)/256, 256>>>(Wk, 2, Cq*Cq/4);
    cvt_kernel<<<(Cq*Cq/4 + 255)/256, 256>>>(Wv, 3, Cq*Cq/4);
    cvt_kernel<<<(Cq*Cq/4 + 255)/256, 256>>>(Wo, 4, Cq*Cq/4);

    // grid.x = N-blocks (16) so consecutive CTAs reuse the same A tile via L2
    qkv_mma_kernel<<<dim3(Cq/128, Mq/128, 3), 256, GEMM_SMEM>>>();
    zero_kv_kernel<<<(Bq*Hq*DHq*DHq + 255)/256, 256>>>();
    kv_kernel<<<dim3(Bq*Hq, Tq/512), 256>>>();
    attn_out_kernel<<<dim3(Bq*Hq, Tq/64), 256, ATT_SMEM>>>();
    out_mma_kernel<<<dim3(Cq/128, Mq/128), 256, GEMM_SMEM>>>(out);
}

// round 8
// speedup vs baseline: 2.7302x; 1.0095x over previous
#include <cuda_runtime.h>
#include <cuda_fp16.h>
#include <cstdint>

// Problem constants
#define Bq   4
#define Tq   4096
#define Cq   2048
#define Hq   16
#define DHq  128
#define Mq   (Bq*Tq)          // 16384
#define BHq  (Bq*Hq)          // 64

// -------- device globals (allocation-free rule) --------
__device__ __half g_xh[Mq*Cq];     // x hi/lo [m][c]
__device__ __half g_xl[Mq*Cq];
__device__ __half g_wh[4*Cq*Cq];   // Wq|Wk|Wv|Wo hi/lo [o][c]
__device__ __half g_wl[4*Cq*Cq];
__device__ __half g_qh[Mq*Cq];     // q = featmap(xWq) hi/lo [bh][t][d]
__device__ __half g_ql[Mq*Cq];
__device__ __half g_kth[Mq*Cq];    // kT = featmap(xWk)^T hi/lo [bh][d][t]
__device__ __half g_ktl[Mq*Cq];
__device__ __half g_vth[Mq*Cq];    // vT = (xWv)^T hi/lo [bh][d][t]
__device__ __half g_vtl[Mq*Cq];
__device__ __half g_kvh[BHq*DHq*DHq];  // kvT[e][d] hi/lo
__device__ __half g_kvl[BHq*DHq*DHq];
__device__ __half g_ath[Mq*Cq];    // attention out hi/lo [b,t,C]
__device__ __half g_atl[Mq*Cq];
__device__ float  g_ksum[BHq*DHq];
__device__ float  g_z[BHq*Tq];

__device__ __forceinline__ float featmap(float y) {
    return y > 0.f ? y + 1.f : __expf(y);   // elu(y)+1
}

__device__ __forceinline__ uint32_t smem_u32(const void* p) {
    uint32_t a;
    asm("{ .reg .u64 t; cvta.to.shared.u64 t, %1; cvt.u32.u64 %0, t; }"
        : "=r"(a) : "l"(p));
    return a;
}

__device__ __forceinline__ void cpa16(uint32_t s, const void* g) {
    asm volatile("cp.async.cg.shared.global [%0], [%1], 16;" :: "r"(s), "l"(g));
}

#define LDSM4(r, a)                                                            \
    asm volatile("ldmatrix.sync.aligned.m8n8.x4.shared.b16 {%0,%1,%2,%3}, [%4];" \
        : "=r"((r)[0]), "=r"((r)[1]), "=r"((r)[2]), "=r"((r)[3]) : "r"(a))

__device__ __forceinline__ void mma16816(float* d, const uint32_t* a, const uint32_t* b)
{
    asm volatile(
        "mma.sync.aligned.m16n8k16.row.col.f32.f16.f16.f32 "
        "{%0,%1,%2,%3}, {%4,%5,%6,%7}, {%8,%9}, {%0,%1,%2,%3};"
        : "+f"(d[0]), "+f"(d[1]), "+f"(d[2]), "+f"(d[3])
        : "r"(a[0]), "r"(a[1]), "r"(a[2]), "r"(a[3]), "r"(b[0]), "r"(b[1]));
}

// ===========================================================================
// fp32 -> (hi, lo) fp16 split elementwise
// ===========================================================================
__global__ void cvt_kernel(const float* __restrict__ src, int dst_sel, int n4)
{
    const int i = blockIdx.x * blockDim.x + threadIdx.x;
    if (i >= n4) return;
    __half *hi, *lo;
    if (dst_sel == 0) { hi = g_xh; lo = g_xl; }
    else {
        hi = g_wh + (size_t)(dst_sel - 1) * Cq * Cq;
        lo = g_wl + (size_t)(dst_sel - 1) * Cq * Cq;
    }
    float4 v = ((const float4*)src)[i];
    __half2 h0 = __floats2half2_rn(v.x, v.y);
    float2  b0 = __half22float2(h0);
    __half2 l0 = __floats2half2_rn(v.x - b0.x, v.y - b0.y);
    __half2 h1 = __floats2half2_rn(v.z, v.w);
    float2  b1 = __half22float2(h1);
    __half2 l1 = __floats2half2_rn(v.z - b1.x, v.w - b1.y);
    ((__half2*)hi)[i*2]   = h0;  ((__half2*)hi)[i*2+1] = h1;
    ((__half2*)lo)[i*2]   = l0;  ((__half2*)lo)[i*2+1] = l1;
}

// ===========================================================================
// Generic 3-product fp16 mma core.  C[m,n] = sum_k A[m,k]*B[n,k]
// CTA tile 128x128, BK=32 halves, cp.async 3-stage + ldmatrix (proven r6 core).
// EPI: 0 = fp32 out (pitch Cq, +bn)
//      1 = featmap -> hi/lo [bh][t][d]            (Q)
//      2 = (act?) -> smem transpose -> hi/lo [bh][d][t]   (K/V)
//      3 = hi/lo [bh][e][d] pitch 128             (kvT)
//      4 = *z -> hi/lo att [b,t,C]                (attn)
// ===========================================================================
#define NST          3
#define STG_BYTES    32768
#define GEMM_SMEM    (NST*STG_BYTES)      // 98304
#define TPITCH       136                  // halves, transpose staging pitch

template<int EPI>
__device__ __forceinline__ void mma_core(
    const __half* __restrict__ Ah_g, const __half* __restrict__ Al_g,
    const __half* __restrict__ Bh_g, const __half* __restrict__ Bl_g,
    int lda, int ldb, int Klen, int bm, int bn, int bh,
    float* __restrict__ out_f32, __half* __restrict__ outh,
    __half* __restrict__ outl, const float* __restrict__ zrow, bool act)
{
    extern __shared__ char sm2[];
    const uint32_t sb = smem_u32(sm2);
    const int tid = threadIdx.x;

    // ---- cp.async mapping: row = tid>>1, two 16B segs at (tid&1)*2 ----
    const int rowG = tid >> 1;
    const int seg0 = (tid & 1) * 2;
    const uint32_t xrg = ((rowG >> 1) & 3) << 4;
    const uint32_t d0 = rowG*64 + (( seg0   *16) ^ xrg);
    const uint32_t d1 = rowG*64 + (((seg0+1)*16) ^ xrg);
    const __half* sAh = Ah_g + (size_t)(bm + rowG) * lda + seg0*8;
    const __half* sAl = Al_g + (size_t)(bm + rowG) * lda + seg0*8;
    const __half* sBh = Bh_g + (size_t)(bn + rowG) * ldb + seg0*8;
    const __half* sBl = Bl_g + (size_t)(bn + rowG) * ldb + seg0*8;

    auto issue = [&](int kc, int slot) {
        const uint32_t b = sb + slot * STG_BYTES;
        const int ko = kc * 32;
        cpa16(b         + d0, sAh + ko);  cpa16(b         + d1, sAh + ko + 8);
        cpa16(b +  8192 + d0, sAl + ko);  cpa16(b +  8192 + d1, sAl + ko + 8);
        cpa16(b + 16384 + d0, sBh + ko);  cpa16(b + 16384 + d1, sBh + ko + 8);
        cpa16(b + 24576 + d0, sBl + ko);  cpa16(b + 24576 + d1, sBl + ko + 8);
        asm volatile("cp.async.commit_group;" ::: "memory");
    };

    issue(0, 0);
    issue(1, 1);

    // ---- fragment mapping ----
    const int wid  = tid >> 5;
    const int lane = tid & 31;
    const int wm = (wid & 3) * 32;
    const int wn = (wid >> 2) * 64;
    const uint32_t xs  = ((lane >> 1) & 3) << 4;
    const uint32_t kqa = (lane >> 4) * 16;
    const uint32_t kqb = ((lane >> 3) & 1) * 16;
    uint32_t saofs[2], sbofs[4];
    #pragma unroll
    for (int mt = 0; mt < 2; mt++)
        saofs[mt] = (uint32_t)(wm + mt*16 + (lane & 15)) * 64;
    #pragma unroll
    for (int p = 0; p < 4; p++)
        sbofs[p] = (uint32_t)(wn + p*16 + ((lane >> 4) & 1)*8 + (lane & 7)) * 64;

    float acc[2][8][4];
    #pragma unroll
    for (int i = 0; i < 2; i++)
        #pragma unroll
        for (int j = 0; j < 8; j++)
            #pragma unroll
            for (int e = 0; e < 4; e++) acc[i][j][e] = 0.f;

    const int NCHUNK = Klen / 32;

    for (int kc = 0; kc < NCHUNK; kc++) {
        if (kc == NCHUNK - 1) asm volatile("cp.async.wait_group 0;" ::: "memory");
        else                  asm volatile("cp.async.wait_group 1;" ::: "memory");
        __syncthreads();
        if (kc + 2 < NCHUNK) issue(kc + 2, (kc + 2) % NST);

        const uint32_t st = sb + (kc % NST) * STG_BYTES;
        #pragma unroll
        for (int ks = 0; ks < 2; ks++) {
            uint32_t ah[2][4], al[2][4];
            const uint32_t ca = (ks*32 + kqa) ^ xs;
            #pragma unroll
            for (int mt = 0; mt < 2; mt++) {
                LDSM4(ah[mt], st +         saofs[mt] + ca);
                LDSM4(al[mt], st +  8192 + saofs[mt] + ca);
            }
            const uint32_t cb = (ks*32 + kqb) ^ xs;
            #pragma unroll
            for (int p = 0; p < 4; p++) {
                uint32_t bh2[4], bl2[4];
                LDSM4(bh2, st + 16384 + sbofs[p] + cb);
                LDSM4(bl2, st + 24576 + sbofs[p] + cb);
                #pragma unroll
                for (int mt = 0; mt < 2; mt++) {
                    mma16816(acc[mt][2*p],   ah[mt], bh2);
                    mma16816(acc[mt][2*p],   ah[mt], bl2);
                    mma16816(acc[mt][2*p],   al[mt], bh2);
                    mma16816(acc[mt][2*p+1], ah[mt], bh2 + 2);
                    mma16816(acc[mt][2*p+1], ah[mt], bl2 + 2);
                    mma16816(acc[mt][2*p+1], al[mt], bh2 + 2);
                }
            }
        }
    }

    // ---- epilogues ----
    const int r0 = lane >> 2;
    const int c0 = (lane & 3) * 2;

    if constexpr (EPI == 2) {
        // transpose via smem, output [bh][d][t]
        __syncthreads();   // all warps done with pipeline smem
        __half* shh = (__half*)sm2;
        __half* shl = shh + 128*TPITCH;
        #pragma unroll
        for (int mt = 0; mt < 2; mt++)
            #pragma unroll
            for (int half = 0; half < 2; half++) {
                const int lm = wm + mt*16 + r0 + half*8;
                #pragma unroll
                for (int nt = 0; nt < 8; nt++) {
                    const int n0 = wn + nt*8 + c0;
                    float v0 = acc[mt][nt][half*2];
                    float v1 = acc[mt][nt][half*2 + 1];
                    if (act) { v0 = featmap(v0); v1 = featmap(v1); }
                    __half h0 = __float2half_rn(v0);
                    __half h1 = __float2half_rn(v1);
                    __half l0 = __float2half_rn(v0 - __half2float(h0));
                    __half l1 = __float2half_rn(v1 - __half2float(h1));
                    shh[ n0   *TPITCH + lm] = h0;
                    shh[(n0+1)*TPITCH + lm] = h1;
                    shl[ n0   *TPITCH + lm] = l0;
                    shl[(n0+1)*TPITCH + lm] = l1;
                }
            }
        __syncthreads();
        const int tloc = bm & (Tq - 1);           // batch-local t offset (r7 bug fix)
        const int dd = tid >> 1;
        const int ts = (tid & 1) * 64;
        const uint4* srcH = (const uint4*)(shh + dd*TPITCH + ts);
        const uint4* srcL = (const uint4*)(shl + dd*TPITCH + ts);
        uint4* dstH = (uint4*)(outh + ((size_t)bh*DHq + dd)*Tq + tloc + ts);
        uint4* dstL = (uint4*)(outl + ((size_t)bh*DHq + dd)*Tq + tloc + ts);
        #pragma unroll
        for (int q = 0; q < 8; q++) { dstH[q] = srcH[q]; dstL[q] = srcL[q]; }
        return;
    }

    #pragma unroll
    for (int mt = 0; mt < 2; mt++) {
        #pragma unroll
        for (int half = 0; half < 2; half++) {
            const int lm = wm + mt*16 + r0 + half*8;
            #pragma unroll
            for (int nt = 0; nt < 8; nt++) {
                const int n0 = wn + nt*8 + c0;
                float v0 = acc[mt][nt][half*2];
                float v1 = acc[mt][nt][half*2 + 1];
                if constexpr (EPI == 0) {
                    float* op = out_f32 + (size_t)(bm + lm) * Cq + bn;
                    *(float2*)(op + n0) = make_float2(v0, v1);
                } else if constexpr (EPI == 1) {
                    if (act) { v0 = featmap(v0); v1 = featmap(v1); }
                    const int t = (bm + lm) & (Tq - 1);
                    const size_t base = ((size_t)bh*Tq + t)*DHq;
                    __half2 h2 = __floats2half2_rn(v0, v1);
                    float2  bk = __half22float2(h2);
                    __half2 l2 = __floats2half2_rn(v0 - bk.x, v1 - bk.y);
                    *(__half2*)&outh[base + n0] = h2;
                    *(__half2*)&outl[base + n0] = l2;
                } else if constexpr (EPI == 3) {
                    const size_t base = ((size_t)bh*DHq + lm)*DHq;
                    __half2 h2 = __floats2half2_rn(v0, v1);
                    float2  bk = __half22float2(h2);
                    __half2 l2 = __floats2half2_rn(v0 - bk.x, v1 - bk.y);
                    *(__half2*)&outh[base + n0] = h2;
                    *(__half2*)&outl[base + n0] = l2;
                } else if constexpr (EPI == 4) {
                    const int t = bm + lm;
                    const float z = zrow[t];
                    v0 *= z; v1 *= z;
                    const size_t base =
                        ((size_t)(bh >> 4)*Tq + t)*Cq + (size_t)(bh & 15)*DHq;
                    __half2 h2 = __floats2half2_rn(v0, v1);
                    float2  bk = __half22float2(h2);
                    __half2 l2 = __floats2half2_rn(v0 - bk.x, v1 - bk.y);
                    *(__half2*)&outh[base + n0] = h2;
                    *(__half2*)&outl[base + n0] = l2;
                }
            }
        }
    }
}

// ---------------------------------------------------------------------------
// kernels
// ---------------------------------------------------------------------------
__global__ __launch_bounds__(256)
void qkv_mma_kernel()
{
    const int h  = blockIdx.x;
    const int bm = blockIdx.y * 128;
    const int z  = blockIdx.z;
    const int bh = ((bm >> 12) << 4) + h;
    const __half* Wh = g_wh + (size_t)z * Cq * Cq;
    const __half* Wl = g_wl + (size_t)z * Cq * Cq;
    if (z == 0)
        mma_core<1>(g_xh, g_xl, Wh, Wl, Cq, Cq, Cq, bm, h*128, bh,
                    nullptr, g_qh, g_ql, nullptr, true);
    else if (z == 1)
        mma_core<2>(g_xh, g_xl, Wh, Wl, Cq, Cq, Cq, bm, h*128, bh,
                    nullptr, g_kth, g_ktl, nullptr, true);
    else
        mma_core<2>(g_xh, g_xl, Wh, Wl, Cq, Cq, Cq, bm, h*128, bh,
                    nullptr, g_vth, g_vtl, nullptr, false);
}

__global__ __launch_bounds__(256)
void kv_mma_kernel()
{
    const int bh = blockIdx.x;
    const size_t o = (size_t)bh * DHq * Tq;
    mma_core<3>(g_vth + o, g_vtl + o, g_kth + o, g_ktl + o,
                Tq, Tq, Tq, 0, 0, bh, nullptr, g_kvh, g_kvl, nullptr, false);
}

__global__ __launch_bounds__(256)
void attn_mma_kernel()
{
    const int bh = blockIdx.x;
    const int bm = blockIdx.y * 128;
    const size_t oq = (size_t)bh * Tq * DHq;
    const size_t ok = (size_t)bh * DHq * DHq;
    mma_core<4>(g_qh + oq, g_ql + oq, g_kvh + ok, g_kvl + ok,
                DHq, DHq, DHq, bm, 0, bh,
                nullptr, g_ath, g_atl, g_z + (size_t)bh * Tq, false);
}

__global__ __launch_bounds__(256)
void out_mma_kernel(float* __restrict__ out)
{
    mma_core<0>(g_ath, g_atl,
                g_wh + (size_t)3*Cq*Cq, g_wl + (size_t)3*Cq*Cq,
                Cq, Cq, Cq, blockIdx.y*128, blockIdx.x*128, 0,
                out, nullptr, nullptr, nullptr, false);
}

// ksum[bh][d] = sum_t kT[bh][d][t]  (hi + lo)
__global__ __launch_bounds__(256)
void ksum_kernel()
{
    const int r    = blockIdx.x * 8 + (threadIdx.x >> 5);   // 0..8191
    const int lane = threadIdx.x & 31;
    const __half2* ph = (const __half2*)(g_kth + (size_t)r * Tq);
    const __half2* pl = (const __half2*)(g_ktl + (size_t)r * Tq);
    float s = 0.f;
    for (int i = lane; i < Tq/2; i += 32) {
        float2 a = __half22float2(ph[i]);
        float2 b = __half22float2(pl[i]);
        s += a.x + a.y + b.x + b.y;
    }
    s += __shfl_xor_sync(0xffffffffu, s, 16);
    s += __shfl_xor_sync(0xffffffffu, s, 8);
    s += __shfl_xor_sync(0xffffffffu, s, 4);
    s += __shfl_xor_sync(0xffffffffu, s, 2);
    s += __shfl_xor_sync(0xffffffffu, s, 1);
    if (lane == 0) g_ksum[r] = s;
}

// z[bh][t] = 1 / (sum_d q[bh][t][d]*ksum[bh][d] + 1e-6)
__global__ __launch_bounds__(256)
void z_kernel()
{
    __shared__ float ks[DHq];
    const int bh = blockIdx.x >> 9;            // 512 blocks per bh
    const int t0 = (blockIdx.x & 511) * 8;
    const int tid  = threadIdx.x;
    const int warp = tid >> 5;
    const int lane = tid & 31;
    if (tid < DHq) ks[tid] = g_ksum[bh*DHq + tid];
    __syncthreads();

    const int t = t0 + warp;
    const __half2* qh2 = (const __half2*)(g_qh + ((size_t)bh*Tq + t)*DHq);
    const __half2* ql2 = (const __half2*)(g_ql + ((size_t)bh*Tq + t)*DHq);
    float2 a0 = __half22float2(qh2[lane*2]);
    float2 a1 = __half22float2(qh2[lane*2+1]);
    float2 b0 = __half22float2(ql2[lane*2]);
    float2 b1 = __half22float2(ql2[lane*2+1]);
    float s = (a0.x + b0.x) * ks[lane*4]
            + (a0.y + b0.y) * ks[lane*4+1]
            + (a1.x + b1.x) * ks[lane*4+2]
            + (a1.y + b1.y) * ks[lane*4+3];
    s += __shfl_xor_sync(0xffffffffu, s, 16);
    s += __shfl_xor_sync(0xffffffffu, s, 8);
    s += __shfl_xor_sync(0xffffffffu, s, 4);
    s += __shfl_xor_sync(0xffffffffu, s, 2);
    s += __shfl_xor_sync(0xffffffffu, s, 1);
    if (lane == 0) g_z[bh*Tq + t] = 1.f / (s + 1e-6f);
}

// ---------------------------------------------------------------------------
extern "C" void kernel_launch(void* const* d_in, const int* in_sizes, int n_in,
                              void* d_out, int out_size)
{
    const float* x  = (const float*)d_in[0];
    // d_in[1] = cos, d_in[2] = sin : unused by the reference module
    const float* Wq = (const float*)d_in[3];
    const float* Wk = (const float*)d_in[4];
    const float* Wv = (const float*)d_in[5];
    const float* Wo = (const float*)d_in[6];
    float* out = (float*)d_out;

    cudaFuncSetAttribute(qkv_mma_kernel,
                         cudaFuncAttributeMaxDynamicSharedMemorySize, GEMM_SMEM);
    cudaFuncSetAttribute(kv_mma_kernel,
                         cudaFuncAttributeMaxDynamicSharedMemorySize, GEMM_SMEM);
    cudaFuncSetAttribute(attn_mma_kernel,
                         cudaFuncAttributeMaxDynamicSharedMemorySize, GEMM_SMEM);
    cudaFuncSetAttribute(out_mma_kernel,
                         cudaFuncAttributeMaxDynamicSharedMemorySize, GEMM_SMEM);

    cvt_kernel<<<(Mq*Cq/4 + 255)/256, 256>>>(x,  0, Mq*Cq/4);
    cvt_kernel<<<(Cq*Cq/4 + 255)/256, 256>>>(Wq, 1, Cq*Cq/4);
    cvt_kernel<<<(Cq*Cq/4 + 255)/256, 256>>>(Wk, 2, Cq*Cq/4);
    cvt_kernel<<<(Cq*Cq/4 + 255)/256, 256>>>(Wv, 3, Cq*Cq/4);
    cvt_kernel<<<(Cq*Cq/4 + 255)/256, 256>>>(Wo, 4, Cq*Cq/4);

    qkv_mma_kernel<<<dim3(Hq, Mq/128, 3), 256, GEMM_SMEM>>>();
    ksum_kernel<<<BHq*DHq/8, 256>>>();
    z_kernel<<<BHq*512, 256>>>();
    kv_mma_kernel<<<BHq, 256, GEMM_SMEM>>>();
    attn_mma_kernel<<<dim3(BHq, Tq/128), 256, GEMM_SMEM>>>();
    out_mma_kernel<<<dim3(Cq/128, Mq/128), 256, GEMM_SMEM>>>(out);
}

// round 9
// speedup vs baseline: 3.5511x; 1.3007x over previous
#include <cuda_runtime.h>
#include <cuda_fp16.h>
#include <cstdint>

// Problem constants
#define Bq   4
#define Tq   4096
#define Cq   2048
#define Hq   16
#define DHq  128
#define Mq   (Bq*Tq)          // 16384
#define BHq  (Bq*Hq)          // 64

// -------- device globals (allocation-free rule) --------
__device__ __half g_xh[Mq*Cq];     // x hi [m][c]  (2-product: lo not needed)
__device__ __half g_wh[4*Cq*Cq];   // Wq|Wk|Wv|Wo hi/lo [o][c]
__device__ __half g_wl[4*Cq*Cq];
__device__ __half g_qh[Mq*Cq];     // q = featmap(xWq) hi/lo [bh][t][d]
__device__ __half g_ql[Mq*Cq];
__device__ __half g_kth[Mq*Cq];    // kT = featmap(xWk)^T hi/lo [bh][d][t]
__device__ __half g_ktl[Mq*Cq];
__device__ __half g_vth[Mq*Cq];    // vT = (xWv)^T hi/lo [bh][d][t]
__device__ __half g_vtl[Mq*Cq];
__device__ __half g_kvh[BHq*DHq*DHq];  // kvT[e][d] hi/lo
__device__ __half g_kvl[BHq*DHq*DHq];
__device__ __half g_ath[Mq*Cq];    // attention out hi [b,t,C]
__device__ float  g_ksum[BHq*DHq];
__device__ float  g_z[BHq*Tq];

__device__ __forceinline__ float featmap(float y) {
    return y > 0.f ? y + 1.f : __expf(y);   // elu(y)+1
}

__device__ __forceinline__ uint32_t smem_u32(const void* p) {
    uint32_t a;
    asm("{ .reg .u64 t; cvta.to.shared.u64 t, %1; cvt.u32.u64 %0, t; }"
        : "=r"(a) : "l"(p));
    return a;
}

__device__ __forceinline__ void cpa16(uint32_t s, const void* g) {
    asm volatile("cp.async.cg.shared.global [%0], [%1], 16;" :: "r"(s), "l"(g));
}

#define LDSM4(r, a)                                                            \
    asm volatile("ldmatrix.sync.aligned.m8n8.x4.shared.b16 {%0,%1,%2,%3}, [%4];" \
        : "=r"((r)[0]), "=r"((r)[1]), "=r"((r)[2]), "=r"((r)[3]) : "r"(a))

__device__ __forceinline__ void mma16816(float* d, const uint32_t* a, const uint32_t* b)
{
    asm volatile(
        "mma.sync.aligned.m16n8k16.row.col.f32.f16.f16.f32 "
        "{%0,%1,%2,%3}, {%4,%5,%6,%7}, {%8,%9}, {%0,%1,%2,%3};"
        : "+f"(d[0]), "+f"(d[1]), "+f"(d[2]), "+f"(d[3])
        : "r"(a[0]), "r"(a[1]), "r"(a[2]), "r"(a[3]), "r"(b[0]), "r"(b[1]));
}

// ===========================================================================
// fp32 -> (hi, lo) fp16 split elementwise.  dst_sel 0 = x (hi only),
// 1..4 = Wq/Wk/Wv/Wo (hi+lo).
// ===========================================================================
__global__ void cvt_kernel(const float* __restrict__ src, int dst_sel, int n4)
{
    const int i = blockIdx.x * blockDim.x + threadIdx.x;
    if (i >= n4) return;
    float4 v = ((const float4*)src)[i];
    __half2 h0 = __floats2half2_rn(v.x, v.y);
    __half2 h1 = __floats2half2_rn(v.z, v.w);
    if (dst_sel == 0) {
        ((__half2*)g_xh)[i*2]   = h0;
        ((__half2*)g_xh)[i*2+1] = h1;
        return;
    }
    __half* hi = g_wh + (size_t)(dst_sel - 1) * Cq * Cq;
    __half* lo = g_wl + (size_t)(dst_sel - 1) * Cq * Cq;
    float2  b0 = __half22float2(h0);
    __half2 l0 = __floats2half2_rn(v.x - b0.x, v.y - b0.y);
    float2  b1 = __half22float2(h1);
    __half2 l1 = __floats2half2_rn(v.z - b1.x, v.w - b1.y);
    ((__half2*)hi)[i*2]   = h0;  ((__half2*)hi)[i*2+1] = h1;
    ((__half2*)lo)[i*2]   = l0;  ((__half2*)lo)[i*2+1] = l1;
}

// ===========================================================================
// Generic fp16 mma core.  C[m,n] = sum_k A[m,k]*B[n,k]
// NPROD=2: a*b ~= ah*(bh+bl)  (A hi-only; stage Ah|Bh|Bl = 24KB, 4-stage pipe)
// NPROD=3: a*b ~= ah*bh + ah*bl + al*bh (stage Ah|Al|Bh|Bl = 32KB, 3-stage)
// EPI: 0 = fp32 out (pitch Cq, +bn)
//      1 = featmap -> hi/lo [bh][t][d]            (Q)
//      2 = (act?) -> smem transpose -> hi/lo [bh][d][t]   (K/V)
//      3 = hi/lo [bh][e][d] pitch 128             (kvT)
//      4 = *z -> hi att [b,t,C]                   (attn)
// ===========================================================================
#define GEMM_SMEM    98304
#define TPITCH       136                  // halves, transpose staging pitch

template<int EPI, int NPROD>
__device__ __forceinline__ void mma_core(
    const __half* __restrict__ Ah_g, const __half* __restrict__ Al_g,
    const __half* __restrict__ Bh_g, const __half* __restrict__ Bl_g,
    int lda, int ldb, int Klen, int bm, int bn, int bh,
    float* __restrict__ out_f32, __half* __restrict__ outh,
    __half* __restrict__ outl, const float* __restrict__ zrow, bool act)
{
    constexpr uint32_t STG  = (NPROD == 2) ? 24576u : 32768u;
    constexpr int      NSTG = (NPROD == 2) ? 4 : 3;
    constexpr uint32_t OBH  = (NPROD == 2) ? 8192u  : 16384u;  // B-hi tile offset
    constexpr uint32_t OBL  = (NPROD == 2) ? 16384u : 24576u;  // B-lo tile offset

    extern __shared__ char sm2[];
    const uint32_t sb = smem_u32(sm2);
    const int tid = threadIdx.x;

    // ---- cp.async mapping: row = tid>>1, two 16B segs at (tid&1)*2 ----
    const int rowG = tid >> 1;
    const int seg0 = (tid & 1) * 2;
    const uint32_t xrg = ((rowG >> 1) & 3) << 4;
    const uint32_t d0 = rowG*64 + (( seg0   *16) ^ xrg);
    const uint32_t d1 = rowG*64 + (((seg0+1)*16) ^ xrg);
    const __half* sAh = Ah_g + (size_t)(bm + rowG) * lda + seg0*8;
    const __half* sAl = Al_g + (size_t)(bm + rowG) * lda + seg0*8;
    const __half* sBh = Bh_g + (size_t)(bn + rowG) * ldb + seg0*8;
    const __half* sBl = Bl_g + (size_t)(bn + rowG) * ldb + seg0*8;

    auto issue = [&](int kc, int slot) {
        const uint32_t b = sb + slot * STG;
        const int ko = kc * 32;
        cpa16(b       + d0, sAh + ko);  cpa16(b       + d1, sAh + ko + 8);
        if (NPROD == 3) {
            cpa16(b + 8192 + d0, sAl + ko);  cpa16(b + 8192 + d1, sAl + ko + 8);
        }
        cpa16(b + OBH + d0, sBh + ko);  cpa16(b + OBH + d1, sBh + ko + 8);
        cpa16(b + OBL + d0, sBl + ko);  cpa16(b + OBL + d1, sBl + ko + 8);
        asm volatile("cp.async.commit_group;" ::: "memory");
    };

    const int NCHUNK = Klen / 32;

    issue(0, 0);
    issue(1, 1);
    if (NPROD == 2 && NCHUNK > 2) issue(2, 2);

    // ---- fragment mapping ----
    const int wid  = tid >> 5;
    const int lane = tid & 31;
    const int wm = (wid & 3) * 32;
    const int wn = (wid >> 2) * 64;
    const uint32_t xs  = ((lane >> 1) & 3) << 4;
    const uint32_t kqa = (lane >> 4) * 16;
    const uint32_t kqb = ((lane >> 3) & 1) * 16;
    uint32_t saofs[2], sbofs[4];
    #pragma unroll
    for (int mt = 0; mt < 2; mt++)
        saofs[mt] = (uint32_t)(wm + mt*16 + (lane & 15)) * 64;
    #pragma unroll
    for (int p = 0; p < 4; p++)
        sbofs[p] = (uint32_t)(wn + p*16 + ((lane >> 4) & 1)*8 + (lane & 7)) * 64;

    float acc[2][8][4];
    #pragma unroll
    for (int i = 0; i < 2; i++)
        #pragma unroll
        for (int j = 0; j < 8; j++)
            #pragma unroll
            for (int e = 0; e < 4; e++) acc[i][j][e] = 0.f;

    for (int kc = 0; kc < NCHUNK; kc++) {
        if (NPROD == 2) {
            if (kc < NCHUNK - 2)       asm volatile("cp.async.wait_group 2;" ::: "memory");
            else if (kc == NCHUNK - 2) asm volatile("cp.async.wait_group 1;" ::: "memory");
            else                       asm volatile("cp.async.wait_group 0;" ::: "memory");
        } else {
            if (kc == NCHUNK - 1) asm volatile("cp.async.wait_group 0;" ::: "memory");
            else                  asm volatile("cp.async.wait_group 1;" ::: "memory");
        }
        __syncthreads();
        if (NPROD == 2) { if (kc + 3 < NCHUNK) issue(kc + 3, (kc + 3) % NSTG); }
        else            { if (kc + 2 < NCHUNK) issue(kc + 2, (kc + 2) % NSTG); }

        const uint32_t st = sb + (kc % NSTG) * STG;
        #pragma unroll
        for (int ks = 0; ks < 2; ks++) {
            uint32_t ah[2][4], al[2][4];
            const uint32_t ca = (ks*32 + kqa) ^ xs;
            #pragma unroll
            for (int mt = 0; mt < 2; mt++) {
                LDSM4(ah[mt], st + saofs[mt] + ca);
                if (NPROD == 3) LDSM4(al[mt], st + 8192 + saofs[mt] + ca);
            }
            const uint32_t cb = (ks*32 + kqb) ^ xs;
            #pragma unroll
            for (int p = 0; p < 4; p++) {
                uint32_t bh2[4], bl2[4];
                LDSM4(bh2, st + OBH + sbofs[p] + cb);
                LDSM4(bl2, st + OBL + sbofs[p] + cb);
                #pragma unroll
                for (int mt = 0; mt < 2; mt++) {
                    mma16816(acc[mt][2*p],   ah[mt], bh2);
                    mma16816(acc[mt][2*p],   ah[mt], bl2);
                    if (NPROD == 3) mma16816(acc[mt][2*p], al[mt], bh2);
                    mma16816(acc[mt][2*p+1], ah[mt], bh2 + 2);
                    mma16816(acc[mt][2*p+1], ah[mt], bl2 + 2);
                    if (NPROD == 3) mma16816(acc[mt][2*p+1], al[mt], bh2 + 2);
                }
            }
        }
    }

    // ---- epilogues ----
    const int r0 = lane >> 2;
    const int c0 = (lane & 3) * 2;

    if constexpr (EPI == 2) {
        // transpose via smem, output [bh][d][t]
        __syncthreads();   // all warps done with pipeline smem
        __half* shh = (__half*)sm2;
        __half* shl = shh + 128*TPITCH;
        #pragma unroll
        for (int mt = 0; mt < 2; mt++)
            #pragma unroll
            for (int half = 0; half < 2; half++) {
                const int lm = wm + mt*16 + r0 + half*8;
                #pragma unroll
                for (int nt = 0; nt < 8; nt++) {
                    const int n0 = wn + nt*8 + c0;
                    float v0 = acc[mt][nt][half*2];
                    float v1 = acc[mt][nt][half*2 + 1];
                    if (act) { v0 = featmap(v0); v1 = featmap(v1); }
                    __half h0 = __float2half_rn(v0);
                    __half h1 = __float2half_rn(v1);
                    __half l0 = __float2half_rn(v0 - __half2float(h0));
                    __half l1 = __float2half_rn(v1 - __half2float(h1));
                    shh[ n0   *TPITCH + lm] = h0;
                    shh[(n0+1)*TPITCH + lm] = h1;
                    shl[ n0   *TPITCH + lm] = l0;
                    shl[(n0+1)*TPITCH + lm] = l1;
                }
            }
        __syncthreads();
        const int tloc = bm & (Tq - 1);           // batch-local t offset
        const int dd = tid >> 1;
        const int ts = (tid & 1) * 64;
        const uint4* srcH = (const uint4*)(shh + dd*TPITCH + ts);
        const uint4* srcL = (const uint4*)(shl + dd*TPITCH + ts);
        uint4* dstH = (uint4*)(outh + ((size_t)bh*DHq + dd)*Tq + tloc + ts);
        uint4* dstL = (uint4*)(outl + ((size_t)bh*DHq + dd)*Tq + tloc + ts);
        #pragma unroll
        for (int q = 0; q < 8; q++) { dstH[q] = srcH[q]; dstL[q] = srcL[q]; }
        return;
    }

    #pragma unroll
    for (int mt = 0; mt < 2; mt++) {
        #pragma unroll
        for (int half = 0; half < 2; half++) {
            const int lm = wm + mt*16 + r0 + half*8;
            #pragma unroll
            for (int nt = 0; nt < 8; nt++) {
                const int n0 = wn + nt*8 + c0;
                float v0 = acc[mt][nt][half*2];
                float v1 = acc[mt][nt][half*2 + 1];
                if constexpr (EPI == 0) {
                    float* op = out_f32 + (size_t)(bm + lm) * Cq + bn;
                    *(float2*)(op + n0) = make_float2(v0, v1);
                } else if constexpr (EPI == 1) {
                    if (act) { v0 = featmap(v0); v1 = featmap(v1); }
                    const int t = (bm + lm) & (Tq - 1);
                    const size_t base = ((size_t)bh*Tq + t)*DHq;
                    __half2 h2 = __floats2half2_rn(v0, v1);
                    float2  bk = __half22float2(h2);
                    __half2 l2 = __floats2half2_rn(v0 - bk.x, v1 - bk.y);
                    *(__half2*)&outh[base + n0] = h2;
                    *(__half2*)&outl[base + n0] = l2;
                } else if constexpr (EPI == 3) {
                    const size_t base = ((size_t)bh*DHq + lm)*DHq;
                    __half2 h2 = __floats2half2_rn(v0, v1);
                    float2  bk = __half22float2(h2);
                    __half2 l2 = __floats2half2_rn(v0 - bk.x, v1 - bk.y);
                    *(__half2*)&outh[base + n0] = h2;
                    *(__half2*)&outl[base + n0] = l2;
                } else if constexpr (EPI == 4) {
                    const int t = bm + lm;
                    const float z = zrow[t];
                    v0 *= z; v1 *= z;
                    const size_t base =
                        ((size_t)(bh >> 4)*Tq + t)*Cq + (size_t)(bh & 15)*DHq;
                    *(__half2*)&outh[base + n0] = __floats2half2_rn(v0, v1);
                }
            }
        }
    }
}

// ---------------------------------------------------------------------------
// kernels
// ---------------------------------------------------------------------------
__global__ __launch_bounds__(256)
void qkv_mma_kernel()
{
    const int h  = blockIdx.x;
    const int bm = blockIdx.y * 128;
    const int z  = blockIdx.z;
    const int bh = ((bm >> 12) << 4) + h;
    const __half* Wh = g_wh + (size_t)z * Cq * Cq;
    const __half* Wl = g_wl + (size_t)z * Cq * Cq;
    if (z == 0)
        mma_core<1, 2>(g_xh, g_xh, Wh, Wl, Cq, Cq, Cq, bm, h*128, bh,
                       nullptr, g_qh, g_ql, nullptr, true);
    else if (z == 1)
        mma_core<2, 2>(g_xh, g_xh, Wh, Wl, Cq, Cq, Cq, bm, h*128, bh,
                       nullptr, g_kth, g_ktl, nullptr, true);
    else
        mma_core<2, 2>(g_xh, g_xh, Wh, Wl, Cq, Cq, Cq, bm, h*128, bh,
                       nullptr, g_vth, g_vtl, nullptr, false);
}

__global__ __launch_bounds__(256)
void kv_mma_kernel()
{
    const int bh = blockIdx.x;
    const size_t o = (size_t)bh * DHq * Tq;
    mma_core<3, 3>(g_vth + o, g_vtl + o, g_kth + o, g_ktl + o,
                   Tq, Tq, Tq, 0, 0, bh, nullptr, g_kvh, g_kvl, nullptr, false);
}

__global__ __launch_bounds__(256)
void attn_mma_kernel()
{
    const int bh = blockIdx.x;
    const int bm = blockIdx.y * 128;
    const size_t oq = (size_t)bh * Tq * DHq;
    const size_t ok = (size_t)bh * DHq * DHq;
    mma_core<4, 3>(g_qh + oq, g_ql + oq, g_kvh + ok, g_kvl + ok,
                   DHq, DHq, DHq, bm, 0, bh,
                   nullptr, g_ath, nullptr, g_z + (size_t)bh * Tq, false);
}

__global__ __launch_bounds__(256)
void out_mma_kernel(float* __restrict__ out)
{
    mma_core<0, 2>(g_ath, g_ath,
                   g_wh + (size_t)3*Cq*Cq, g_wl + (size_t)3*Cq*Cq,
                   Cq, Cq, Cq, blockIdx.y*128, blockIdx.x*128, 0,
                   out, nullptr, nullptr, nullptr, false);
}

// ksum[bh][d] = sum_t kT[bh][d][t]  (hi + lo)
__global__ __launch_bounds__(256)
void ksum_kernel()
{
    const int r    = blockIdx.x * 8 + (threadIdx.x >> 5);   // 0..8191
    const int lane = threadIdx.x & 31;
    const __half2* ph = (const __half2*)(g_kth + (size_t)r * Tq);
    const __half2* pl = (const __half2*)(g_ktl + (size_t)r * Tq);
    float s = 0.f;
    for (int i = lane; i < Tq/2; i += 32) {
        float2 a = __half22float2(ph[i]);
        float2 b = __half22float2(pl[i]);
        s += a.x + a.y + b.x + b.y;
    }
    s += __shfl_xor_sync(0xffffffffu, s, 16);
    s += __shfl_xor_sync(0xffffffffu, s, 8);
    s += __shfl_xor_sync(0xffffffffu, s, 4);
    s += __shfl_xor_sync(0xffffffffu, s, 2);
    s += __shfl_xor_sync(0xffffffffu, s, 1);
    if (lane == 0) g_ksum[r] = s;
}

// z[bh][t] = 1 / (sum_d q[bh][t][d]*ksum[bh][d] + 1e-6)
__global__ __launch_bounds__(256)
void z_kernel()
{
    __shared__ float ks[DHq];
    const int bh = blockIdx.x >> 9;            // 512 blocks per bh
    const int t0 = (blockIdx.x & 511) * 8;
    const int tid  = threadIdx.x;
    const int warp = tid >> 5;
    const int lane = tid & 31;
    if (tid < DHq) ks[tid] = g_ksum[bh*DHq + tid];
    __syncthreads();

    const int t = t0 + warp;
    const __half2* qh2 = (const __half2*)(g_qh + ((size_t)bh*Tq + t)*DHq);
    const __half2* ql2 = (const __half2*)(g_ql + ((size_t)bh*Tq + t)*DHq);
    float2 a0 = __half22float2(qh2[lane*2]);
    float2 a1 = __half22float2(qh2[lane*2+1]);
    float2 b0 = __half22float2(ql2[lane*2]);
    float2 b1 = __half22float2(ql2[lane*2+1]);
    float s = (a0.x + b0.x) * ks[lane*4]
            + (a0.y + b0.y) * ks[lane*4+1]
            + (a1.x + b1.x) * ks[lane*4+2]
            + (a1.y + b1.y) * ks[lane*4+3];
    s += __shfl_xor_sync(0xffffffffu, s, 16);
    s += __shfl_xor_sync(0xffffffffu, s, 8);
    s += __shfl_xor_sync(0xffffffffu, s, 4);
    s += __shfl_xor_sync(0xffffffffu, s, 2);
    s += __shfl_xor_sync(0xffffffffu, s, 1);
    if (lane == 0) g_z[bh*Tq + t] = 1.f / (s + 1e-6f);
}

// ---------------------------------------------------------------------------
extern "C" void kernel_launch(void* const* d_in, const int* in_sizes, int n_in,
                              void* d_out, int out_size)
{
    const float* x  = (const float*)d_in[0];
    // d_in[1] = cos, d_in[2] = sin : unused by the reference module
    const float* Wq = (const float*)d_in[3];
    const float* Wk = (const float*)d_in[4];
    const float* Wv = (const float*)d_in[5];
    const float* Wo = (const float*)d_in[6];
    float* out = (float*)d_out;

    cudaFuncSetAttribute(qkv_mma_kernel,
                         cudaFuncAttributeMaxDynamicSharedMemorySize, GEMM_SMEM);
    cudaFuncSetAttribute(kv_mma_kernel,
                         cudaFuncAttributeMaxDynamicSharedMemorySize, GEMM_SMEM);
    cudaFuncSetAttribute(attn_mma_kernel,
                         cudaFuncAttributeMaxDynamicSharedMemorySize, GEMM_SMEM);
    cudaFuncSetAttribute(out_mma_kernel,
                         cudaFuncAttributeMaxDynamicSharedMemorySize, GEMM_SMEM);

    cvt_kernel<<<(Mq*Cq/4 + 255)/256, 256>>>(x,  0, Mq*Cq/4);
    cvt_kernel<<<(Cq*Cq/4 + 255)/256, 256>>>(Wq, 1, Cq*Cq/4);
    cvt_kernel<<<(Cq*Cq/4 + 255)/256, 256>>>(Wk, 2, Cq*Cq/4);
    cvt_kernel<<<(Cq*Cq/4 + 255)/256, 256>>>(Wv, 3, Cq*Cq/4);
    cvt_kernel<<<(Cq*Cq/4 + 255)/256, 256>>>(Wo, 4, Cq*Cq/4);

    qkv_mma_kernel<<<dim3(Hq, Mq/128, 3), 256, GEMM_SMEM>>>();
    ksum_kernel<<<BHq*DHq/8, 256>>>();
    z_kernel<<<BHq*512, 256>>>();
    kv_mma_kernel<<<BHq, 256, GEMM_SMEM>>>();
    attn_mma_kernel<<<dim3(BHq, Tq/128), 256, GEMM_SMEM>>>();
    out_mma_kernel<<<dim3(Cq/128, Mq/128), 256, GEMM_SMEM>>>(out);
}

// round 10
// speedup vs baseline: 3.7981x; 1.0696x over previous
#include <cuda_runtime.h>
#include <cuda_fp16.h>
#include <cstdint>

// Problem constants
#define Bq   4
#define Tq   4096
#define Cq   2048
#define Hq   16
#define DHq  128
#define Mq   (Bq*Tq)          // 16384
#define BHq  (Bq*Hq)          // 64

// -------- device globals (allocation-free rule) --------
__device__ __half g_xh[Mq*Cq];     // x hi [m][c]  (2-product: lo not needed)
__device__ __half g_wh[4*Cq*Cq];   // Wq|Wk|Wv|Wo hi/lo [o][c]
__device__ __half g_wl[4*Cq*Cq];
__device__ __half g_qh[Mq*Cq];     // q = featmap(xWq) hi/lo [bh][t][d]
__device__ __half g_ql[Mq*Cq];
__device__ __half g_kth[Mq*Cq];    // kT = featmap(xWk)^T hi/lo [bh][d][t]
__device__ __half g_ktl[Mq*Cq];
__device__ __half g_vth[Mq*Cq];    // vT = (xWv)^T hi/lo [bh][d][t]
__device__ __half g_vtl[Mq*Cq];
__device__ __half g_kvh[BHq*DHq*DHq];  // kvT[e][d] hi/lo
__device__ __half g_kvl[BHq*DHq*DHq];
__device__ __half g_ath[Mq*Cq];    // attention out hi [b,t,C]
__device__ float  g_ksum[BHq*DHq];
__device__ float  g_z[BHq*Tq];

__device__ __forceinline__ float featmap(float y) {
    return y > 0.f ? y + 1.f : __expf(y);   // elu(y)+1
}

__device__ __forceinline__ uint32_t smem_u32(const void* p) {
    uint32_t a;
    asm("{ .reg .u64 t; cvta.to.shared.u64 t, %1; cvt.u32.u64 %0, t; }"
        : "=r"(a) : "l"(p));
    return a;
}

__device__ __forceinline__ void cpa16(uint32_t s, const void* g) {
    asm volatile("cp.async.cg.shared.global [%0], [%1], 16;" :: "r"(s), "l"(g));
}

#define LDSM4(r, a)                                                            \
    asm volatile("ldmatrix.sync.aligned.m8n8.x4.shared.b16 {%0,%1,%2,%3}, [%4];" \
        : "=r"((r)[0]), "=r"((r)[1]), "=r"((r)[2]), "=r"((r)[3]) : "r"(a))

__device__ __forceinline__ void mma16816(float* d, const uint32_t* a, const uint32_t* b)
{
    asm volatile(
        "mma.sync.aligned.m16n8k16.row.col.f32.f16.f16.f32 "
        "{%0,%1,%2,%3}, {%4,%5,%6,%7}, {%8,%9}, {%0,%1,%2,%3};"
        : "+f"(d[0]), "+f"(d[1]), "+f"(d[2]), "+f"(d[3])
        : "r"(a[0]), "r"(a[1]), "r"(a[2]), "r"(a[3]), "r"(b[0]), "r"(b[1]));
}

// ===========================================================================
// fp32 -> (hi, lo) fp16 split elementwise.  dst_sel 0 = x (hi only),
// 1..4 = Wq/Wk/Wv/Wo (hi+lo).
// ===========================================================================
__global__ void cvt_kernel(const float* __restrict__ src, int dst_sel, int n4)
{
    const int i = blockIdx.x * blockDim.x + threadIdx.x;
    if (i >= n4) return;
    float4 v = ((const float4*)src)[i];
    __half2 h0 = __floats2half2_rn(v.x, v.y);
    __half2 h1 = __floats2half2_rn(v.z, v.w);
    if (dst_sel == 0) {
        ((__half2*)g_xh)[i*2]   = h0;
        ((__half2*)g_xh)[i*2+1] = h1;
        return;
    }
    __half* hi = g_wh + (size_t)(dst_sel - 1) * Cq * Cq;
    __half* lo = g_wl + (size_t)(dst_sel - 1) * Cq * Cq;
    float2  b0 = __half22float2(h0);
    __half2 l0 = __floats2half2_rn(v.x - b0.x, v.y - b0.y);
    float2  b1 = __half22float2(h1);
    __half2 l1 = __floats2half2_rn(v.z - b1.x, v.w - b1.y);
    ((__half2*)hi)[i*2]   = h0;  ((__half2*)hi)[i*2+1] = h1;
    ((__half2*)lo)[i*2]   = l0;  ((__half2*)lo)[i*2+1] = l1;
}

// ===========================================================================
// Generic fp16 mma core.  C[m,n] = sum_k A[m,k]*B[n,k]
// NPROD=2: a*b ~= ah*(bh+bl)  (A hi-only; stage Ah|Bh|Bl = 24KB, 4-stage pipe)
// NPROD=3: a*b ~= ah*bh + ah*bl + al*bh (stage Ah|Al|Bh|Bl = 32KB, 3-stage)
// EPI: 0 = fp32 out (pitch Cq, +bn)
//      1 = featmap -> hi/lo [bh][t][d]            (Q)
//      2 = (act?) -> smem transpose -> hi/lo [bh][d][t]   (K/V)
//      3 = hi/lo [bh][e][d] pitch 128             (kvT)
//      4 = *z -> hi att [b,t,C]                   (attn)
// ===========================================================================
#define GEMM_SMEM    98304
#define TPITCH       136                  // halves, transpose staging pitch

template<int EPI, int NPROD>
__device__ __forceinline__ void mma_core(
    const __half* __restrict__ Ah_g, const __half* __restrict__ Al_g,
    const __half* __restrict__ Bh_g, const __half* __restrict__ Bl_g,
    int lda, int ldb, int Klen, int bm, int bn, int bh,
    float* __restrict__ out_f32, __half* __restrict__ outh,
    __half* __restrict__ outl, const float* __restrict__ zrow, bool act)
{
    constexpr uint32_t STG  = (NPROD == 2) ? 24576u : 32768u;
    constexpr int      NSTG = (NPROD == 2) ? 4 : 3;
    constexpr uint32_t OBH  = (NPROD == 2) ? 8192u  : 16384u;  // B-hi tile offset
    constexpr uint32_t OBL  = (NPROD == 2) ? 16384u : 24576u;  // B-lo tile offset

    extern __shared__ char sm2[];
    const uint32_t sb = smem_u32(sm2);
    const int tid = threadIdx.x;

    // ---- cp.async mapping: row = tid>>1, two 16B segs at (tid&1)*2 ----
    const int rowG = tid >> 1;
    const int seg0 = (tid & 1) * 2;
    const uint32_t xrg = ((rowG >> 1) & 3) << 4;
    const uint32_t d0 = rowG*64 + (( seg0   *16) ^ xrg);
    const uint32_t d1 = rowG*64 + (((seg0+1)*16) ^ xrg);
    const __half* sAh = Ah_g + (size_t)(bm + rowG) * lda + seg0*8;
    const __half* sAl = Al_g + (size_t)(bm + rowG) * lda + seg0*8;
    const __half* sBh = Bh_g + (size_t)(bn + rowG) * ldb + seg0*8;
    const __half* sBl = Bl_g + (size_t)(bn + rowG) * ldb + seg0*8;

    auto issue = [&](int kc, int slot) {
        const uint32_t b = sb + slot * STG;
        const int ko = kc * 32;
        cpa16(b       + d0, sAh + ko);  cpa16(b       + d1, sAh + ko + 8);
        if (NPROD == 3) {
            cpa16(b + 8192 + d0, sAl + ko);  cpa16(b + 8192 + d1, sAl + ko + 8);
        }
        cpa16(b + OBH + d0, sBh + ko);  cpa16(b + OBH + d1, sBh + ko + 8);
        cpa16(b + OBL + d0, sBl + ko);  cpa16(b + OBL + d1, sBl + ko + 8);
        asm volatile("cp.async.commit_group;" ::: "memory");
    };

    const int NCHUNK = Klen / 32;

    issue(0, 0);
    issue(1, 1);
    if (NPROD == 2 && NCHUNK > 2) issue(2, 2);

    // ---- fragment mapping ----
    const int wid  = tid >> 5;
    const int lane = tid & 31;
    const int wm = (wid & 3) * 32;
    const int wn = (wid >> 2) * 64;
    const uint32_t xs  = ((lane >> 1) & 3) << 4;
    const uint32_t kqa = (lane >> 4) * 16;
    const uint32_t kqb = ((lane >> 3) & 1) * 16;
    uint32_t saofs[2], sbofs[4];
    #pragma unroll
    for (int mt = 0; mt < 2; mt++)
        saofs[mt] = (uint32_t)(wm + mt*16 + (lane & 15)) * 64;
    #pragma unroll
    for (int p = 0; p < 4; p++)
        sbofs[p] = (uint32_t)(wn + p*16 + ((lane >> 4) & 1)*8 + (lane & 7)) * 64;

    float acc[2][8][4];
    #pragma unroll
    for (int i = 0; i < 2; i++)
        #pragma unroll
        for (int j = 0; j < 8; j++)
            #pragma unroll
            for (int e = 0; e < 4; e++) acc[i][j][e] = 0.f;

    for (int kc = 0; kc < NCHUNK; kc++) {
        if (NPROD == 2) {
            if (kc < NCHUNK - 2)       asm volatile("cp.async.wait_group 2;" ::: "memory");
            else if (kc == NCHUNK - 2) asm volatile("cp.async.wait_group 1;" ::: "memory");
            else                       asm volatile("cp.async.wait_group 0;" ::: "memory");
        } else {
            if (kc == NCHUNK - 1) asm volatile("cp.async.wait_group 0;" ::: "memory");
            else                  asm volatile("cp.async.wait_group 1;" ::: "memory");
        }
        __syncthreads();
        if (NPROD == 2) { if (kc + 3 < NCHUNK) issue(kc + 3, (kc + 3) % NSTG); }
        else            { if (kc + 2 < NCHUNK) issue(kc + 2, (kc + 2) % NSTG); }

        const uint32_t st = sb + (kc % NSTG) * STG;
        #pragma unroll
        for (int ks = 0; ks < 2; ks++) {
            uint32_t ah[2][4], al[2][4];
            const uint32_t ca = (ks*32 + kqa) ^ xs;
            #pragma unroll
            for (int mt = 0; mt < 2; mt++) {
                LDSM4(ah[mt], st + saofs[mt] + ca);
                if (NPROD == 3) LDSM4(al[mt], st + 8192 + saofs[mt] + ca);
            }
            const uint32_t cb = (ks*32 + kqb) ^ xs;
            #pragma unroll
            for (int p = 0; p < 4; p++) {
                uint32_t bh2[4], bl2[4];
                LDSM4(bh2, st + OBH + sbofs[p] + cb);
                LDSM4(bl2, st + OBL + sbofs[p] + cb);
                #pragma unroll
                for (int mt = 0; mt < 2; mt++) {
                    mma16816(acc[mt][2*p],   ah[mt], bh2);
                    mma16816(acc[mt][2*p],   ah[mt], bl2);
                    if (NPROD == 3) mma16816(acc[mt][2*p], al[mt], bh2);
                    mma16816(acc[mt][2*p+1], ah[mt], bh2 + 2);
                    mma16816(acc[mt][2*p+1], ah[mt], bl2 + 2);
                    if (NPROD == 3) mma16816(acc[mt][2*p+1], al[mt], bh2 + 2);
                }
            }
        }
    }

    // ---- epilogues ----
    const int r0 = lane >> 2;
    const int c0 = (lane & 3) * 2;

    if constexpr (EPI == 2) {
        // transpose via smem, output [bh][d][t]
        __syncthreads();   // all warps done with pipeline smem
        __half* shh = (__half*)sm2;
        __half* shl = shh + 128*TPITCH;
        #pragma unroll
        for (int mt = 0; mt < 2; mt++)
            #pragma unroll
            for (int half = 0; half < 2; half++) {
                const int lm = wm + mt*16 + r0 + half*8;
                #pragma unroll
                for (int nt = 0; nt < 8; nt++) {
                    const int n0 = wn + nt*8 + c0;
                    float v0 = acc[mt][nt][half*2];
                    float v1 = acc[mt][nt][half*2 + 1];
                    if (act) { v0 = featmap(v0); v1 = featmap(v1); }
                    __half h0 = __float2half_rn(v0);
                    __half h1 = __float2half_rn(v1);
                    __half l0 = __float2half_rn(v0 - __half2float(h0));
                    __half l1 = __float2half_rn(v1 - __half2float(h1));
                    shh[ n0   *TPITCH + lm] = h0;
                    shh[(n0+1)*TPITCH + lm] = h1;
                    shl[ n0   *TPITCH + lm] = l0;
                    shl[(n0+1)*TPITCH + lm] = l1;
                }
            }
        __syncthreads();
        const int tloc = bm & (Tq - 1);           // batch-local t offset
        const int dd = tid >> 1;
        const int ts = (tid & 1) * 64;
        const uint4* srcH = (const uint4*)(shh + dd*TPITCH + ts);
        const uint4* srcL = (const uint4*)(shl + dd*TPITCH + ts);
        uint4* dstH = (uint4*)(outh + ((size_t)bh*DHq + dd)*Tq + tloc + ts);
        uint4* dstL = (uint4*)(outl + ((size_t)bh*DHq + dd)*Tq + tloc + ts);
        #pragma unroll
        for (int q = 0; q < 8; q++) { dstH[q] = srcH[q]; dstL[q] = srcL[q]; }
        return;
    }

    #pragma unroll
    for (int mt = 0; mt < 2; mt++) {
        #pragma unroll
        for (int half = 0; half < 2; half++) {
            const int lm = wm + mt*16 + r0 + half*8;
            #pragma unroll
            for (int nt = 0; nt < 8; nt++) {
                const int n0 = wn + nt*8 + c0;
                float v0 = acc[mt][nt][half*2];
                float v1 = acc[mt][nt][half*2 + 1];
                if constexpr (EPI == 0) {
                    float* op = out_f32 + (size_t)(bm + lm) * Cq + bn;
                    *(float2*)(op + n0) = make_float2(v0, v1);
                } else if constexpr (EPI == 1) {
                    if (act) { v0 = featmap(v0); v1 = featmap(v1); }
                    const int t = (bm + lm) & (Tq - 1);
                    const size_t base = ((size_t)bh*Tq + t)*DHq;
                    __half2 h2 = __floats2half2_rn(v0, v1);
                    float2  bk = __half22float2(h2);
                    __half2 l2 = __floats2half2_rn(v0 - bk.x, v1 - bk.y);
                    *(__half2*)&outh[base + n0] = h2;
                    *(__half2*)&outl[base + n0] = l2;
                } else if constexpr (EPI == 3) {
                    const size_t base = ((size_t)bh*DHq + lm)*DHq;
                    __half2 h2 = __floats2half2_rn(v0, v1);
                    float2  bk = __half22float2(h2);
                    __half2 l2 = __floats2half2_rn(v0 - bk.x, v1 - bk.y);
                    *(__half2*)&outh[base + n0] = h2;
                    *(__half2*)&outl[base + n0] = l2;
                } else if constexpr (EPI == 4) {
                    const int t = bm + lm;
                    const float z = zrow[t];
                    v0 *= z; v1 *= z;
                    const size_t base =
                        ((size_t)(bh >> 4)*Tq + t)*Cq + (size_t)(bh & 15)*DHq;
                    *(__half2*)&outh[base + n0] = __floats2half2_rn(v0, v1);
                }
            }
        }
    }
}

// ---------------------------------------------------------------------------
// kernels  (min-blocks 2: cap regs at 128 -> 2 CTAs/SM, 4 warps/SMSP)
// ---------------------------------------------------------------------------
__global__ __launch_bounds__(256, 2)
void qkv_mma_kernel()
{
    const int h  = blockIdx.x;
    const int bm = blockIdx.y * 128;
    const int z  = blockIdx.z;
    const int bh = ((bm >> 12) << 4) + h;
    const __half* Wh = g_wh + (size_t)z * Cq * Cq;
    const __half* Wl = g_wl + (size_t)z * Cq * Cq;
    if (z == 0)
        mma_core<1, 2>(g_xh, g_xh, Wh, Wl, Cq, Cq, Cq, bm, h*128, bh,
                       nullptr, g_qh, g_ql, nullptr, true);
    else if (z == 1)
        mma_core<2, 2>(g_xh, g_xh, Wh, Wl, Cq, Cq, Cq, bm, h*128, bh,
                       nullptr, g_kth, g_ktl, nullptr, true);
    else
        mma_core<2, 2>(g_xh, g_xh, Wh, Wl, Cq, Cq, Cq, bm, h*128, bh,
                       nullptr, g_vth, g_vtl, nullptr, false);
}

__global__ __launch_bounds__(256, 2)
void kv_mma_kernel()
{
    const int bh = blockIdx.x;
    const size_t o = (size_t)bh * DHq * Tq;
    mma_core<3, 3>(g_vth + o, g_vtl + o, g_kth + o, g_ktl + o,
                   Tq, Tq, Tq, 0, 0, bh, nullptr, g_kvh, g_kvl, nullptr, false);
}

__global__ __launch_bounds__(256, 2)
void attn_mma_kernel()
{
    const int bh = blockIdx.x;
    const int bm = blockIdx.y * 128;
    const size_t oq = (size_t)bh * Tq * DHq;
    const size_t ok = (size_t)bh * DHq * DHq;
    mma_core<4, 3>(g_qh + oq, g_ql + oq, g_kvh + ok, g_kvl + ok,
                   DHq, DHq, DHq, bm, 0, bh,
                   nullptr, g_ath, nullptr, g_z + (size_t)bh * Tq, false);
}

__global__ __launch_bounds__(256, 2)
void out_mma_kernel(float* __restrict__ out)
{
    mma_core<0, 2>(g_ath, g_ath,
                   g_wh + (size_t)3*Cq*Cq, g_wl + (size_t)3*Cq*Cq,
                   Cq, Cq, Cq, blockIdx.y*128, blockIdx.x*128, 0,
                   out, nullptr, nullptr, nullptr, false);
}

// ksum[bh][d] = sum_t kT[bh][d][t]  (hi + lo)
__global__ __launch_bounds__(256)
void ksum_kernel()
{
    const int r    = blockIdx.x * 8 + (threadIdx.x >> 5);   // 0..8191
    const int lane = threadIdx.x & 31;
    const __half2* ph = (const __half2*)(g_kth + (size_t)r * Tq);
    const __half2* pl = (const __half2*)(g_ktl + (size_t)r * Tq);
    float s = 0.f;
    for (int i = lane; i < Tq/2; i += 32) {
        float2 a = __half22float2(ph[i]);
        float2 b = __half22float2(pl[i]);
        s += a.x + a.y + b.x + b.y;
    }
    s += __shfl_xor_sync(0xffffffffu, s, 16);
    s += __shfl_xor_sync(0xffffffffu, s, 8);
    s += __shfl_xor_sync(0xffffffffu, s, 4);
    s += __shfl_xor_sync(0xffffffffu, s, 2);
    s += __shfl_xor_sync(0xffffffffu, s, 1);
    if (lane == 0) g_ksum[r] = s;
}

// z[bh][t] = 1 / (sum_d q[bh][t][d]*ksum[bh][d] + 1e-6)
__global__ __launch_bounds__(256)
void z_kernel()
{
    __shared__ float ks[DHq];
    const int bh = blockIdx.x >> 9;            // 512 blocks per bh
    const int t0 = (blockIdx.x & 511) * 8;
    const int tid  = threadIdx.x;
    const int warp = tid >> 5;
    const int lane = tid & 31;
    if (tid < DHq) ks[tid] = g_ksum[bh*DHq + tid];
    __syncthreads();

    const int t = t0 + warp;
    const __half2* qh2 = (const __half2*)(g_qh + ((size_t)bh*Tq + t)*DHq);
    const __half2* ql2 = (const __half2*)(g_ql + ((size_t)bh*Tq + t)*DHq);
    float2 a0 = __half22float2(qh2[lane*2]);
    float2 a1 = __half22float2(qh2[lane*2+1]);
    float2 b0 = __half22float2(ql2[lane*2]);
    float2 b1 = __half22float2(ql2[lane*2+1]);
    float s = (a0.x + b0.x) * ks[lane*4]
            + (a0.y + b0.y) * ks[lane*4+1]
            + (a1.x + b1.x) * ks[lane*4+2]
            + (a1.y + b1.y) * ks[lane*4+3];
    s += __shfl_xor_sync(0xffffffffu, s, 16);
    s += __shfl_xor_sync(0xffffffffu, s, 8);
    s += __shfl_xor_sync(0xffffffffu, s, 4);
    s += __shfl_xor_sync(0xffffffffu, s, 2);
    s += __shfl_xor_sync(0xffffffffu, s, 1);
    if (lane == 0) g_z[bh*Tq + t] = 1.f / (s + 1e-6f);
}

// ---------------------------------------------------------------------------
extern "C" void kernel_launch(void* const* d_in, const int* in_sizes, int n_in,
                              void* d_out, int out_size)
{
    const float* x  = (const float*)d_in[0];
    // d_in[1] = cos, d_in[2] = sin : unused by the reference module
    const float* Wq = (const float*)d_in[3];
    const float* Wk = (const float*)d_in[4];
    const float* Wv = (const float*)d_in[5];
    const float* Wo = (const float*)d_in[6];
    float* out = (float*)d_out;

    cudaFuncSetAttribute(qkv_mma_kernel,
                         cudaFuncAttributeMaxDynamicSharedMemorySize, GEMM_SMEM);
    cudaFuncSetAttribute(kv_mma_kernel,
                         cudaFuncAttributeMaxDynamicSharedMemorySize, GEMM_SMEM);
    cudaFuncSetAttribute(attn_mma_kernel,
                         cudaFuncAttributeMaxDynamicSharedMemorySize, GEMM_SMEM);
    cudaFuncSetAttribute(out_mma_kernel,
                         cudaFuncAttributeMaxDynamicSharedMemorySize, GEMM_SMEM);

    cvt_kernel<<<(Mq*Cq/4 + 255)/256, 256>>>(x,  0, Mq*Cq/4);
    cvt_kernel<<<(Cq*Cq/4 + 255)/256, 256>>>(Wq, 1, Cq*Cq/4);
    cvt_kernel<<<(Cq*Cq/4 + 255)/256, 256>>>(Wk, 2, Cq*Cq/4);
    cvt_kernel<<<(Cq*Cq/4 + 255)/256, 256>>>(Wv, 3, Cq*Cq/4);
    cvt_kernel<<<(Cq*Cq/4 + 255)/256, 256>>>(Wo, 4, Cq*Cq/4);

    qkv_mma_kernel<<<dim3(Hq, Mq/128, 3), 256, GEMM_SMEM>>>();
    ksum_kernel<<<BHq*DHq/8, 256>>>();
    z_kernel<<<BHq*512, 256>>>();
    kv_mma_kernel<<<BHq, 256, GEMM_SMEM>>>();
    attn_mma_kernel<<<dim3(BHq, Tq/128), 256, GEMM_SMEM>>>();
    out_mma_kernel<<<dim3(Cq/128, Mq/128), 256, GEMM_SMEM>>>(out);
}

// round 11
// speedup vs baseline: 3.8098x; 1.0031x over previous
#include <cuda_runtime.h>
#include <cuda_fp16.h>
#include <cstdint>

// Problem constants
#define Bq   4
#define Tq   4096
#define Cq   2048
#define Hq   16
#define DHq  128
#define Mq   (Bq*Tq)          // 16384
#define BHq  (Bq*Hq)          // 64

// -------- device globals (allocation-free rule) --------
__device__ __half g_xh[Mq*Cq];     // x hi [m][c]
__device__ __half g_wh[4*Cq*Cq];   // Wq|Wk|Wv|Wo hi/lo [o][c]
__device__ __half g_wl[4*Cq*Cq];
__device__ __half g_qh[Mq*Cq];     // q hi/lo [bh][t][d]
__device__ __half g_ql[Mq*Cq];
__device__ __half g_kth[Mq*Cq];    // kT hi/lo [bh][d][t]
__device__ __half g_ktl[Mq*Cq];
__device__ __half g_vth[Mq*Cq];    // vT hi/lo [bh][d][t]
__device__ __half g_vtl[Mq*Cq];
__device__ __half g_kvh[BHq*DHq*DHq];  // kvT[e][d] hi/lo
__device__ __half g_kvl[BHq*DHq*DHq];
__device__ __half g_ath[Mq*Cq];    // attention out hi [b,t,C]
__device__ float  g_ksum[BHq*DHq];
__device__ float  g_z[BHq*Tq];

__device__ __forceinline__ float featmap(float y) {
    return y > 0.f ? y + 1.f : __expf(y);   // elu(y)+1
}

__device__ __forceinline__ uint32_t smem_u32(const void* p) {
    uint32_t a;
    asm("{ .reg .u64 t; cvta.to.shared.u64 t, %1; cvt.u32.u64 %0, t; }"
        : "=r"(a) : "l"(p));
    return a;
}

__device__ __forceinline__ void cpa16(uint32_t s, const void* g) {
    asm volatile("cp.async.cg.shared.global [%0], [%1], 16;" :: "r"(s), "l"(g));
}

#define LDSM4(r, a)                                                            \
    asm volatile("ldmatrix.sync.aligned.m8n8.x4.shared.b16 {%0,%1,%2,%3}, [%4];" \
        : "=r"((r)[0]), "=r"((r)[1]), "=r"((r)[2]), "=r"((r)[3]) : "r"(a))

__device__ __forceinline__ void mma16816(float* d, const uint32_t* a, const uint32_t* b)
{
    asm volatile(
        "mma.sync.aligned.m16n8k16.row.col.f32.f16.f16.f32 "
        "{%0,%1,%2,%3}, {%4,%5,%6,%7}, {%8,%9}, {%0,%1,%2,%3};"
        : "+f"(d[0]), "+f"(d[1]), "+f"(d[2]), "+f"(d[3])
        : "r"(a[0]), "r"(a[1]), "r"(a[2]), "r"(a[3]), "r"(b[0]), "r"(b[1]));
}

// ===========================================================================
// fp32 -> (hi, lo) fp16 split elementwise.
// ===========================================================================
__global__ void cvt_kernel(const float* __restrict__ src, int dst_sel, int n4)
{
    const int i = blockIdx.x * blockDim.x + threadIdx.x;
    if (i >= n4) return;
    float4 v = ((const float4*)src)[i];
    __half2 h0 = __floats2half2_rn(v.x, v.y);
    __half2 h1 = __floats2half2_rn(v.z, v.w);
    if (dst_sel == 0) {
        ((__half2*)g_xh)[i*2]   = h0;
        ((__half2*)g_xh)[i*2+1] = h1;
        return;
    }
    __half* hi = g_wh + (size_t)(dst_sel - 1) * Cq * Cq;
    __half* lo = g_wl + (size_t)(dst_sel - 1) * Cq * Cq;
    float2  b0 = __half22float2(h0);
    __half2 l0 = __floats2half2_rn(v.x - b0.x, v.y - b0.y);
    float2  b1 = __half22float2(h1);
    __half2 l1 = __floats2half2_rn(v.z - b1.x, v.w - b1.y);
    ((__half2*)hi)[i*2]   = h0;  ((__half2*)hi)[i*2+1] = h1;
    ((__half2*)lo)[i*2]   = l0;  ((__half2*)lo)[i*2+1] = l1;
}

#define GEMM_SMEM    98304
#define TPITCH       136

// ===========================================================================
// BIG core: 256x128 CTA tile, 512 threads (16 warps, 4m x 4n, warp 64x32),
// BK=32, 2-product (A hi; B hi+lo).  Stage = A16K|Bh8K|Bl8K = 32KB, 3 stages.
// EPI: 0 = fp32 out; 1 = featmap -> q hi/lo [bh][t][d];
//      2 = (act?) -> transpose (two 128-row halves) -> hi/lo [bh][d][t]
// ===========================================================================
template<int EPI>
__device__ __forceinline__ void mma_big(
    const __half* __restrict__ Ah_g,
    const __half* __restrict__ Bh_g, const __half* __restrict__ Bl_g,
    int lda, int ldb, int bmG, int bn, int bh,
    float* __restrict__ out_f32, __half* __restrict__ outh,
    __half* __restrict__ outl, bool act)
{
    extern __shared__ char sm2[];
    const uint32_t sb = smem_u32(sm2);
    const int tid = threadIdx.x;

    // ---- cp.async mapping: rows 0..255 (tid>>1), two 16B segs ----
    const int rowG = tid >> 1;
    const int seg0 = (tid & 1) * 2;
    const uint32_t xrg = ((rowG >> 1) & 3) << 4;
    const uint32_t d0 = rowG*64 + (( seg0   *16) ^ xrg);
    const uint32_t d1 = rowG*64 + (((seg0+1)*16) ^ xrg);
    const __half* sA = Ah_g + (size_t)(bmG + rowG) * lda + seg0*8;
    const __half* sB = (rowG < 128)
        ? Bh_g + (size_t)(bn + rowG)       * ldb + seg0*8
        : Bl_g + (size_t)(bn + rowG - 128) * ldb + seg0*8;

    auto issue = [&](int kc, int slot) {
        const uint32_t b = sb + slot * 32768u;
        const int ko = kc * 32;
        cpa16(b          + d0, sA + ko);  cpa16(b          + d1, sA + ko + 8);
        cpa16(b + 16384u + d0, sB + ko);  cpa16(b + 16384u + d1, sB + ko + 8);
        asm volatile("cp.async.commit_group;" ::: "memory");
    };

    issue(0, 0);
    issue(1, 1);

    // ---- fragment mapping ----
    const int wid  = tid >> 5;
    const int lane = tid & 31;
    const int wm = (wid & 3) * 64;       // 0,64,128,192
    const int wn = (wid >> 2) * 32;      // 0,32,64,96
    const uint32_t xs  = ((lane >> 1) & 3) << 4;
    const uint32_t kqa = (lane >> 4) * 16;
    const uint32_t kqb = ((lane >> 3) & 1) * 16;
    uint32_t saofs[4], sbofs[2];
    #pragma unroll
    for (int mt = 0; mt < 4; mt++)
        saofs[mt] = (uint32_t)(wm + mt*16 + (lane & 15)) * 64;
    #pragma unroll
    for (int p = 0; p < 2; p++)
        sbofs[p] = (uint32_t)(wn + p*16 + ((lane >> 4) & 1)*8 + (lane & 7)) * 64;

    float acc[4][4][4];
    #pragma unroll
    for (int i = 0; i < 4; i++)
        #pragma unroll
        for (int j = 0; j < 4; j++)
            #pragma unroll
            for (int e = 0; e < 4; e++) acc[i][j][e] = 0.f;

    const int NCHUNK = Cq / 32;   // 64

    for (int kc = 0; kc < NCHUNK; kc++) {
        if (kc == NCHUNK - 1) asm volatile("cp.async.wait_group 0;" ::: "memory");
        else                  asm volatile("cp.async.wait_group 1;" ::: "memory");
        __syncthreads();
        if (kc + 2 < NCHUNK) issue(kc + 2, (kc + 2) % 3);

        const uint32_t st = sb + (kc % 3) * 32768u;
        #pragma unroll
        for (int ks = 0; ks < 2; ks++) {
            uint32_t ah[4][4];
            const uint32_t ca = (ks*32 + kqa) ^ xs;
            #pragma unroll
            for (int mt = 0; mt < 4; mt++)
                LDSM4(ah[mt], st + saofs[mt] + ca);
            const uint32_t cb = (ks*32 + kqb) ^ xs;
            #pragma unroll
            for (int p = 0; p < 2; p++) {
                uint32_t bh2[4], bl2[4];
                LDSM4(bh2, st + 16384u + sbofs[p] + cb);
                LDSM4(bl2, st + 24576u + sbofs[p] + cb);
                #pragma unroll
                for (int mt = 0; mt < 4; mt++) {
                    mma16816(acc[mt][2*p],   ah[mt], bh2);
                    mma16816(acc[mt][2*p],   ah[mt], bl2);
                    mma16816(acc[mt][2*p+1], ah[mt], bh2 + 2);
                    mma16816(acc[mt][2*p+1], ah[mt], bl2 + 2);
                }
            }
        }
    }

    // ---- epilogues ----
    const int r0 = lane >> 2;
    const int c0 = (lane & 3) * 2;

    if constexpr (EPI == 2) {
        // transpose via smem in two 128-t-row halves, output [bh][d][t]
        __syncthreads();
        __half* shh = (__half*)sm2;
        __half* shl = shh + 128*TPITCH;
        const int myhh = (wid & 3) >> 1;          // which t-half this warp owns
        #pragma unroll
        for (int hh = 0; hh < 2; hh++) {
            if (myhh == hh) {
                #pragma unroll
                for (int mt = 0; mt < 4; mt++)
                    #pragma unroll
                    for (int half = 0; half < 2; half++) {
                        const int lt = (wm + mt*16 + r0 + half*8) & 127;
                        #pragma unroll
                        for (int nt = 0; nt < 4; nt++) {
                            const int n0 = wn + nt*8 + c0;
                            float v0 = acc[mt][nt][half*2];
                            float v1 = acc[mt][nt][half*2 + 1];
                            if (act) { v0 = featmap(v0); v1 = featmap(v1); }
                            __half h0 = __float2half_rn(v0);
                            __half h1 = __float2half_rn(v1);
                            __half l0 = __float2half_rn(v0 - __half2float(h0));
                            __half l1 = __float2half_rn(v1 - __half2float(h1));
                            shh[ n0   *TPITCH + lt] = h0;
                            shh[(n0+1)*TPITCH + lt] = h1;
                            shl[ n0   *TPITCH + lt] = l0;
                            shl[(n0+1)*TPITCH + lt] = l1;
                        }
                    }
            }
            __syncthreads();
            const int dd = tid >> 2;              // 0..127
            const int ts = (tid & 3) * 32;        // t offset in half
            const int tdst = (bmG & (Tq - 1)) + hh*128 + ts;
            const uint4* srcH = (const uint4*)(shh + dd*TPITCH + ts);
            const uint4* srcL = (const uint4*)(shl + dd*TPITCH + ts);
            uint4* dstH = (uint4*)(outh + ((size_t)bh*DHq + dd)*Tq + tdst);
            uint4* dstL = (uint4*)(outl + ((size_t)bh*DHq + dd)*Tq + tdst);
            #pragma unroll
            for (int q = 0; q < 4; q++) { dstH[q] = srcH[q]; dstL[q] = srcL[q]; }
            __syncthreads();
        }
        return;
    }

    #pragma unroll
    for (int mt = 0; mt < 4; mt++) {
        #pragma unroll
        for (int half = 0; half < 2; half++) {
            const int lm = wm + mt*16 + r0 + half*8;
            #pragma unroll
            for (int nt = 0; nt < 4; nt++) {
                const int n0 = wn + nt*8 + c0;
                float v0 = acc[mt][nt][half*2];
                float v1 = acc[mt][nt][half*2 + 1];
                if constexpr (EPI == 0) {
                    float* op = out_f32 + (size_t)(bmG + lm) * Cq + bn;
                    *(float2*)(op + n0) = make_float2(v0, v1);
                } else if constexpr (EPI == 1) {
                    if (act) { v0 = featmap(v0); v1 = featmap(v1); }
                    const int t = (bmG + lm) & (Tq - 1);
                    const size_t base = ((size_t)bh*Tq + t)*DHq;
                    __half2 h2 = __floats2half2_rn(v0, v1);
                    float2  bk = __half22float2(h2);
                    __half2 l2 = __floats2half2_rn(v0 - bk.x, v1 - bk.y);
                    *(__half2*)&outh[base + n0] = h2;
                    *(__half2*)&outl[base + n0] = l2;
                }
            }
        }
    }
}

// ===========================================================================
// Old 128x128 3-product core for kv (EPI 3) and attn (EPI 4).
// ===========================================================================
template<int EPI>
__device__ __forceinline__ void mma_core(
    const __half* __restrict__ Ah_g, const __half* __restrict__ Al_g,
    const __half* __restrict__ Bh_g, const __half* __restrict__ Bl_g,
    int lda, int ldb, int Klen, int bm, int bn, int bh,
    __half* __restrict__ outh, __half* __restrict__ outl,
    const float* __restrict__ zrow)
{
    extern __shared__ char sm2[];
    const uint32_t sb = smem_u32(sm2);
    const int tid = threadIdx.x;

    const int rowG = tid >> 1;
    const int seg0 = (tid & 1) * 2;
    const uint32_t xrg = ((rowG >> 1) & 3) << 4;
    const uint32_t d0 = rowG*64 + (( seg0   *16) ^ xrg);
    const uint32_t d1 = rowG*64 + (((seg0+1)*16) ^ xrg);
    const __half* sAh = Ah_g + (size_t)(bm + rowG) * lda + seg0*8;
    const __half* sAl = Al_g + (size_t)(bm + rowG) * lda + seg0*8;
    const __half* sBh = Bh_g + (size_t)(bn + rowG) * ldb + seg0*8;
    const __half* sBl = Bl_g + (size_t)(bn + rowG) * ldb + seg0*8;

    auto issue = [&](int kc, int slot) {
        const uint32_t b = sb + slot * 32768u;
        const int ko = kc * 32;
        cpa16(b          + d0, sAh + ko);  cpa16(b          + d1, sAh + ko + 8);
        cpa16(b +  8192u + d0, sAl + ko);  cpa16(b +  8192u + d1, sAl + ko + 8);
        cpa16(b + 16384u + d0, sBh + ko);  cpa16(b + 16384u + d1, sBh + ko + 8);
        cpa16(b + 24576u + d0, sBl + ko);  cpa16(b + 24576u + d1, sBl + ko + 8);
        asm volatile("cp.async.commit_group;" ::: "memory");
    };

    issue(0, 0);
    issue(1, 1);

    const int wid  = tid >> 5;
    const int lane = tid & 31;
    const int wm = (wid & 3) * 32;
    const int wn = (wid >> 2) * 64;
    const uint32_t xs  = ((lane >> 1) & 3) << 4;
    const uint32_t kqa = (lane >> 4) * 16;
    const uint32_t kqb = ((lane >> 3) & 1) * 16;
    uint32_t saofs[2], sbofs[4];
    #pragma unroll
    for (int mt = 0; mt < 2; mt++)
        saofs[mt] = (uint32_t)(wm + mt*16 + (lane & 15)) * 64;
    #pragma unroll
    for (int p = 0; p < 4; p++)
        sbofs[p] = (uint32_t)(wn + p*16 + ((lane >> 4) & 1)*8 + (lane & 7)) * 64;

    float acc[2][8][4];
    #pragma unroll
    for (int i = 0; i < 2; i++)
        #pragma unroll
        for (int j = 0; j < 8; j++)
            #pragma unroll
            for (int e = 0; e < 4; e++) acc[i][j][e] = 0.f;

    const int NCHUNK = Klen / 32;

    for (int kc = 0; kc < NCHUNK; kc++) {
        if (kc == NCHUNK - 1) asm volatile("cp.async.wait_group 0;" ::: "memory");
        else                  asm volatile("cp.async.wait_group 1;" ::: "memory");
        __syncthreads();
        if (kc + 2 < NCHUNK) issue(kc + 2, (kc + 2) % 3);

        const uint32_t st = sb + (kc % 3) * 32768u;
        #pragma unroll
        for (int ks = 0; ks < 2; ks++) {
            uint32_t ah[2][4], al[2][4];
            const uint32_t ca = (ks*32 + kqa) ^ xs;
            #pragma unroll
            for (int mt = 0; mt < 2; mt++) {
                LDSM4(ah[mt], st + saofs[mt] + ca);
                LDSM4(al[mt], st + 8192u + saofs[mt] + ca);
            }
            const uint32_t cb = (ks*32 + kqb) ^ xs;
            #pragma unroll
            for (int p = 0; p < 4; p++) {
                uint32_t bh2[4], bl2[4];
                LDSM4(bh2, st + 16384u + sbofs[p] + cb);
                LDSM4(bl2, st + 24576u + sbofs[p] + cb);
                #pragma unroll
                for (int mt = 0; mt < 2; mt++) {
                    mma16816(acc[mt][2*p],   ah[mt], bh2);
                    mma16816(acc[mt][2*p],   ah[mt], bl2);
                    mma16816(acc[mt][2*p],   al[mt], bh2);
                    mma16816(acc[mt][2*p+1], ah[mt], bh2 + 2);
                    mma16816(acc[mt][2*p+1], ah[mt], bl2 + 2);
                    mma16816(acc[mt][2*p+1], al[mt], bh2 + 2);
                }
            }
        }
    }

    const int r0 = lane >> 2;
    const int c0 = (lane & 3) * 2;

    #pragma unroll
    for (int mt = 0; mt < 2; mt++) {
        #pragma unroll
        for (int half = 0; half < 2; half++) {
            const int lm = wm + mt*16 + r0 + half*8;
            #pragma unroll
            for (int nt = 0; nt < 8; nt++) {
                const int n0 = wn + nt*8 + c0;
                float v0 = acc[mt][nt][half*2];
                float v1 = acc[mt][nt][half*2 + 1];
                if constexpr (EPI == 3) {
                    const size_t base = ((size_t)bh*DHq + lm)*DHq;
                    __half2 h2 = __floats2half2_rn(v0, v1);
                    float2  bk = __half22float2(h2);
                    __half2 l2 = __floats2half2_rn(v0 - bk.x, v1 - bk.y);
                    *(__half2*)&outh[base + n0] = h2;
                    *(__half2*)&outl[base + n0] = l2;
                } else {    // EPI == 4
                    const int t = bm + lm;
                    const float z = zrow[t];
                    v0 *= z; v1 *= z;
                    const size_t base =
                        ((size_t)(bh >> 4)*Tq + t)*Cq + (size_t)(bh & 15)*DHq;
                    *(__half2*)&outh[base + n0] = __floats2half2_rn(v0, v1);
                }
            }
        }
    }
}

// ---------------------------------------------------------------------------
// kernels
// ---------------------------------------------------------------------------
__global__ __launch_bounds__(512, 1)
void qkv_mma_kernel()
{
    const int h   = blockIdx.x;
    const int bmG = blockIdx.y * 256;
    const int z   = blockIdx.z;
    const int bh  = ((bmG >> 12) << 4) + h;
    const __half* Wh = g_wh + (size_t)z * Cq * Cq;
    const __half* Wl = g_wl + (size_t)z * Cq * Cq;
    if (z == 0)
        mma_big<1>(g_xh, Wh, Wl, Cq, Cq, bmG, h*128, bh,
                   nullptr, g_qh, g_ql, true);
    else if (z == 1)
        mma_big<2>(g_xh, Wh, Wl, Cq, Cq, bmG, h*128, bh,
                   nullptr, g_kth, g_ktl, true);
    else
        mma_big<2>(g_xh, Wh, Wl, Cq, Cq, bmG, h*128, bh,
                   nullptr, g_vth, g_vtl, false);
}

__global__ __launch_bounds__(512, 1)
void out_mma_kernel(float* __restrict__ out)
{
    mma_big<0>(g_ath, g_wh + (size_t)3*Cq*Cq, g_wl + (size_t)3*Cq*Cq,
               Cq, Cq, blockIdx.y*256, blockIdx.x*128, 0,
               out, nullptr, nullptr, false);
}

__global__ __launch_bounds__(256, 2)
void kv_mma_kernel()
{
    const int bh = blockIdx.x;
    const size_t o = (size_t)bh * DHq * Tq;
    mma_core<3>(g_vth + o, g_vtl + o, g_kth + o, g_ktl + o,
                Tq, Tq, Tq, 0, 0, bh, g_kvh, g_kvl, nullptr);
}

__global__ __launch_bounds__(256, 2)
void attn_mma_kernel()
{
    const int bh = blockIdx.x;
    const int bm = blockIdx.y * 128;
    const size_t oq = (size_t)bh * Tq * DHq;
    const size_t ok = (size_t)bh * DHq * DHq;
    mma_core<4>(g_qh + oq, g_ql + oq, g_kvh + ok, g_kvl + ok,
                DHq, DHq, DHq, bm, 0, bh,
                g_ath, nullptr, g_z + (size_t)bh * Tq);
}

// ksum[bh][d] = sum_t kT[bh][d][t]  (hi + lo)
__global__ __launch_bounds__(256)
void ksum_kernel()
{
    const int r    = blockIdx.x * 8 + (threadIdx.x >> 5);
    const int lane = threadIdx.x & 31;
    const __half2* ph = (const __half2*)(g_kth + (size_t)r * Tq);
    const __half2* pl = (const __half2*)(g_ktl + (size_t)r * Tq);
    float s = 0.f;
    for (int i = lane; i < Tq/2; i += 32) {
        float2 a = __half22float2(ph[i]);
        float2 b = __half22float2(pl[i]);
        s += a.x + a.y + b.x + b.y;
    }
    s += __shfl_xor_sync(0xffffffffu, s, 16);
    s += __shfl_xor_sync(0xffffffffu, s, 8);
    s += __shfl_xor_sync(0xffffffffu, s, 4);
    s += __shfl_xor_sync(0xffffffffu, s, 2);
    s += __shfl_xor_sync(0xffffffffu, s, 1);
    if (lane == 0) g_ksum[r] = s;
}

// z[bh][t] = 1 / (sum_d q[bh][t][d]*ksum[bh][d] + 1e-6)
__global__ __launch_bounds__(256)
void z_kernel()
{
    __shared__ float ks[DHq];
    const int bh = blockIdx.x >> 9;
    const int t0 = (blockIdx.x & 511) * 8;
    const int tid  = threadIdx.x;
    const int warp = tid >> 5;
    const int lane = tid & 31;
    if (tid < DHq) ks[tid] = g_ksum[bh*DHq + tid];
    __syncthreads();

    const int t = t0 + warp;
    const __half2* qh2 = (const __half2*)(g_qh + ((size_t)bh*Tq + t)*DHq);
    const __half2* ql2 = (const __half2*)(g_ql + ((size_t)bh*Tq + t)*DHq);
    float2 a0 = __half22float2(qh2[lane*2]);
    float2 a1 = __half22float2(qh2[lane*2+1]);
    float2 b0 = __half22float2(ql2[lane*2]);
    float2 b1 = __half22float2(ql2[lane*2+1]);
    float s = (a0.x + b0.x) * ks[lane*4]
            + (a0.y + b0.y) * ks[lane*4+1]
            + (a1.x + b1.x) * ks[lane*4+2]
            + (a1.y + b1.y) * ks[lane*4+3];
    s += __shfl_xor_sync(0xffffffffu, s, 16);
    s += __shfl_xor_sync(0xffffffffu, s, 8);
    s += __shfl_xor_sync(0xffffffffu, s, 4);
    s += __shfl_xor_sync(0xffffffffu, s, 2);
    s += __shfl_xor_sync(0xffffffffu, s, 1);
    if (lane == 0) g_z[bh*Tq + t] = 1.f / (s + 1e-6f);
}

// ---------------------------------------------------------------------------
extern "C" void kernel_launch(void* const* d_in, const int* in_sizes, int n_in,
                              void* d_out, int out_size)
{
    const float* x  = (const float*)d_in[0];
    // d_in[1] = cos, d_in[2] = sin : unused by the reference module
    const float* Wq = (const float*)d_in[3];
    const float* Wk = (const float*)d_in[4];
    const float* Wv = (const float*)d_in[5];
    const float* Wo = (const float*)d_in[6];
    float* out = (float*)d_out;

    cudaFuncSetAttribute(qkv_mma_kernel,
                         cudaFuncAttributeMaxDynamicSharedMemorySize, GEMM_SMEM);
    cudaFuncSetAttribute(out_mma_kernel,
                         cudaFuncAttributeMaxDynamicSharedMemorySize, GEMM_SMEM);
    cudaFuncSetAttribute(kv_mma_kernel,
                         cudaFuncAttributeMaxDynamicSharedMemorySize, GEMM_SMEM);
    cudaFuncSetAttribute(attn_mma_kernel,
                         cudaFuncAttributeMaxDynamicSharedMemorySize, GEMM_SMEM);

    cvt_kernel<<<(Mq*Cq/4 + 255)/256, 256>>>(x,  0, Mq*Cq/4);
    cvt_kernel<<<(Cq*Cq/4 + 255)/256, 256>>>(Wq, 1, Cq*Cq/4);
    cvt_kernel<<<(Cq*Cq/4 + 255)/256, 256>>>(Wk, 2, Cq*Cq/4);
    cvt_kernel<<<(Cq*Cq/4 + 255)/256, 256>>>(Wv, 3, Cq*Cq/4);
    cvt_kernel<<<(Cq*Cq/4 + 255)/256, 256>>>(Wo, 4, Cq*Cq/4);

    qkv_mma_kernel<<<dim3(Hq, Mq/256, 3), 512, GEMM_SMEM>>>();
    ksum_kernel<<<BHq*DHq/8, 256>>>();
    z_kernel<<<BHq*512, 256>>>();
    kv_mma_kernel<<<BHq, 256, GEMM_SMEM>>>();
    attn_mma_kernel<<<dim3(BHq, Tq/128), 256, GEMM_SMEM>>>();
    out_mma_kernel<<<dim3(Cq/128, Mq/256), 512, GEMM_SMEM>>>(out);
}